// round 6
// baseline (speedup 1.0000x reference)
#include <cuda_runtime.h>
#include <math.h>
#include <stdint.h>

#define N1CAP 50000
#define E1CAP 1000000
#define N2CAP 256
#define E2CAP 4096
#define FDIM 128
#define ODIM 64
#define BGR 10
#define KSEL 50
#define NN2 199

typedef unsigned long long u64;

// ---------------- scratch (device globals; no allocation allowed) ----------------
__device__ int   g_deg1[N1CAP], g_wpos1[N1CAP], g_rowptr1[N1CAP + 1];
__device__ int   g_col1[E1CAP];
__device__ int   g_deg2[N2CAP], g_wpos2[N2CAP], g_rowptr2[N2CAP + 1];
__device__ int   g_col2[E2CAP];
__device__ int   g_part1[128], g_part2[128];
__device__ float g_mean1[(size_t)N1CAP * FDIM];
__device__ float g_h1[(size_t)N1CAP * FDIM];
__device__ float g_o1[(size_t)N1CAP * ODIM];
__device__ float g_mean2[N2CAP * FDIM];
__device__ float g_h2[N2CAP * FDIM];
__device__ float g_o2[N2CAP * ODIM];
__device__ float g_lastcol[N1CAP];
__device__ u64   g_pk[BGR * 8 * KSEL];
__device__ int   g_topk[BGR * KSEL];
__device__ float g_feat[BGR * KSEL * NN2];
__device__ float g_z1[BGR * FDIM];
__device__ float g_y1[BGR * FDIM];

// ---------------- CSR build ----------------
__global__ void zero_counts_kernel(int n1, int n2) {
    int i = blockIdx.x * blockDim.x + threadIdx.x;
    if (i < n1) { g_deg1[i] = 0; g_wpos1[i] = 0; }
    if (i < n2) { g_deg2[i] = 0; g_wpos2[i] = 0; }
}

__global__ void degree_kernel(const int* __restrict__ ei, int E, int* __restrict__ deg) {
    int e = blockIdx.x * blockDim.x + threadIdx.x;
    if (e < E) atomicAdd(&deg[ei[E + e]], 1);
}

__global__ void block_sum_kernel(const int* __restrict__ deg, int n, int* __restrict__ part) {
    __shared__ int s[256];
    int b = blockIdx.x;
    int base = b * 1024;
    int sum = 0;
    for (int i = threadIdx.x; i < 1024; i += 256) {
        int gi = base + i;
        if (gi < n) sum += deg[gi];
    }
    s[threadIdx.x] = sum;
    __syncthreads();
    for (int st = 128; st > 0; st >>= 1) {
        if (threadIdx.x < st) s[threadIdx.x] += s[threadIdx.x + st];
        __syncthreads();
    }
    if (threadIdx.x == 0) part[b] = s[0];
}

__global__ void scan_part_kernel(int* __restrict__ part, int nb, int* __restrict__ rowptr, int n) {
    __shared__ int s[128];
    int t = threadIdx.x;
    int v = (t < nb) ? part[t] : 0;
    s[t] = v;
    __syncthreads();
    for (int off = 1; off < 128; off <<= 1) {
        int u = (t >= off) ? s[t - off] : 0;
        __syncthreads();
        s[t] += u;
        __syncthreads();
    }
    if (t < nb) part[t] = s[t] - v;
    if (t == 127) rowptr[n] = s[127];
}

__global__ void write_rowptr_kernel(const int* __restrict__ deg, int n,
                                    const int* __restrict__ part, int* __restrict__ rowptr) {
    __shared__ int s[1024];
    int b = blockIdx.x, t = threadIdx.x;
    int gi = b * 1024 + t;
    int v = (gi < n) ? deg[gi] : 0;
    s[t] = v;
    __syncthreads();
    for (int off = 1; off < 1024; off <<= 1) {
        int u = (t >= off) ? s[t - off] : 0;
        __syncthreads();
        s[t] += u;
        __syncthreads();
    }
    if (gi < n) rowptr[gi] = part[b] + s[t] - v;
}

__global__ void scatter_kernel(const int* __restrict__ ei, int E,
                               const int* __restrict__ rowptr, int* __restrict__ wpos,
                               int* __restrict__ col) {
    int e = blockIdx.x * blockDim.x + threadIdx.x;
    if (e >= E) return;
    int d = ei[E + e];
    int p = atomicAdd(&wpos[d], 1);
    col[rowptr[d] + p] = ei[e];
}

// ---------------- mean aggregation: warp per node, float4 lanes ----------------
__global__ void aggregate_kernel(const float* __restrict__ x, const int* __restrict__ rowptr,
                                 const int* __restrict__ col, float* __restrict__ out, int n) {
    int w = (blockIdx.x * blockDim.x + threadIdx.x) >> 5;
    int lane = threadIdx.x & 31;
    if (w >= n) return;
    int s = rowptr[w], e = rowptr[w + 1];
    const float4* x4 = (const float4*)x;
    float4 acc = make_float4(0.f, 0.f, 0.f, 0.f);
    #pragma unroll 4
    for (int j = s; j < e; j++) {
        float4 v = x4[(long long)col[j] * 32 + lane];
        acc.x += v.x; acc.y += v.y; acc.z += v.z; acc.w += v.w;
    }
    float inv = 1.0f / (float)max(e - s, 1);
    acc.x *= inv; acc.y *= inv; acc.z *= inv; acc.w *= inv;
    ((float4*)out)[(long long)w * 32 + lane] = acc;
}

// ================= mma.sync 3xTF32 GEMM =================
// out[m, o] = relu( sum_k A0[m,k] W0[o,k] + sum_k A1[m,k] W1[o,k] + bias[o] )
// CTA: 128 threads, tile M=64 x N=NTW*32, K=256 (8 chunks of 32).
// Operands staged in smem in m16n8k8 FRAGMENT ORDER: conflict-free LDS.128/LDS.64.
// 3xTF32: hi*hi + hi*lo + lo*hi, fp32 accumulate in registers.

__device__ __forceinline__ void tf32split(float v, uint32_t& hi, uint32_t& lo) {
    asm("cvt.rna.tf32.f32 %0, %1;" : "=r"(hi) : "f"(v));
    float l = v - __uint_as_float(hi);
    asm("cvt.rna.tf32.f32 %0, %1;" : "=r"(lo) : "f"(l));
}

#define MMA_TF32(ac, a, b0v, b1v) \
    asm volatile("mma.sync.aligned.m16n8k8.row.col.f32.tf32.tf32.f32 " \
                 "{%0,%1,%2,%3}, {%4,%5,%6,%7}, {%8,%9}, {%0,%1,%2,%3};" \
                 : "+f"((ac)[0]), "+f"((ac)[1]), "+f"((ac)[2]), "+f"((ac)[3]) \
                 : "r"((a)[0]), "r"((a)[1]), "r"((a)[2]), "r"((a)[3]), \
                   "r"(b0v), "r"(b1v))

template <int NTW>
__global__ void __launch_bounds__(128)
gemm_mma_kernel(const float* __restrict__ A0, const float* __restrict__ A1,
                const float* __restrict__ W0, const float* __restrict__ W1,
                const float* __restrict__ bias, float* __restrict__ out, int n) {
    constexpr int N = NTW * 32;
    extern __shared__ uint32_t sh[];
    uint32_t* Ah = sh;               // [4 mt][4 k8][32 lane][4 slot] = 2048 u32
    uint32_t* Al = Ah + 2048;
    uint32_t* Bh = Al + 2048;        // [N/8 nt][4 k8][32 lane][2 slot] = N*32 u32
    uint32_t* Bl = Bh + N * 32;

    int tid = threadIdx.x, wid = tid >> 5, lane = tid & 31;
    int gid = lane >> 2, tig = lane & 3;
    long long mbase = (long long)blockIdx.x * 64;

    float acc[4][NTW][4];
    #pragma unroll
    for (int mt = 0; mt < 4; mt++)
        #pragma unroll
        for (int nt = 0; nt < NTW; nt++)
            #pragma unroll
            for (int j = 0; j < 4; j++) acc[mt][nt][j] = 0.f;

    const int nA4 = 512;        // A float4s per chunk (64 rows x 8)
    const int nB4 = N * 8;      // B float4s per chunk

    for (int c = 0; c < 8; c++) {
        const float* Asrc = (c < 4) ? A0 : A1;
        const float* Wsrc = (c < 4) ? W0 : W1;
        int gk = (c & 3) * 32;
        for (int q = tid; q < nA4 + nB4; q += 128) {
            if (q < nA4) {
                int m = q >> 3, k0 = (q & 7) * 4;
                long long node = mbase + m;
                float4 v = make_float4(0.f, 0.f, 0.f, 0.f);
                if (node < n) v = *(const float4*)(Asrc + node * 128 + gk + k0);
                float vv[4] = {v.x, v.y, v.z, v.w};
                int mt = m >> 4, mi = m & 15;
                #pragma unroll
                for (int e = 0; e < 4; e++) {
                    int k = k0 + e;
                    uint32_t hi, lo;
                    tf32split(vv[e], hi, lo);
                    int idx = ((mt * 4 + (k >> 3)) * 32 + (mi & 7) * 4 + (k & 3)) * 4
                              + (mi >> 3) + 2 * ((k >> 2) & 1);
                    Ah[idx] = hi; Al[idx] = lo;
                }
            } else {
                int qq = q - nA4;
                int o = qq >> 3, k0 = (qq & 7) * 4;
                float4 v = *(const float4*)(Wsrc + o * 128 + gk + k0);
                float vv[4] = {v.x, v.y, v.z, v.w};
                int nt = o >> 3, ni = o & 7;
                #pragma unroll
                for (int e = 0; e < 4; e++) {
                    int k = k0 + e;
                    uint32_t hi, lo;
                    tf32split(vv[e], hi, lo);
                    int idx = ((nt * 4 + (k >> 3)) * 32 + ni * 4 + (k & 3)) * 2
                              + ((k >> 2) & 1);
                    Bh[idx] = hi; Bl[idx] = lo;
                }
            }
        }
        __syncthreads();
        #pragma unroll
        for (int k8 = 0; k8 < 4; k8++) {
            uint32_t ah[4][4], al[4][4];
            #pragma unroll
            for (int mt = 0; mt < 4; mt++) {
                int fi = ((mt * 4 + k8) * 32 + lane) * 4;
                uint4 h = *(const uint4*)(Ah + fi);
                uint4 l = *(const uint4*)(Al + fi);
                ah[mt][0] = h.x; ah[mt][1] = h.y; ah[mt][2] = h.z; ah[mt][3] = h.w;
                al[mt][0] = l.x; al[mt][1] = l.y; al[mt][2] = l.z; al[mt][3] = l.w;
            }
            #pragma unroll
            for (int nt = 0; nt < NTW; nt++) {
                int gnt = wid * NTW + nt;
                int bi = ((gnt * 4 + k8) * 32 + lane) * 2;
                uint2 bh = *(const uint2*)(Bh + bi);
                uint2 bl = *(const uint2*)(Bl + bi);
                #pragma unroll
                for (int mt = 0; mt < 4; mt++) {
                    MMA_TF32(acc[mt][nt], ah[mt], bh.x, bh.y);
                    MMA_TF32(acc[mt][nt], ah[mt], bl.x, bl.y);
                    MMA_TF32(acc[mt][nt], al[mt], bh.x, bh.y);
                }
            }
        }
        __syncthreads();
    }

    // epilogue: bias + relu, direct float2 stores
    #pragma unroll
    for (int nt = 0; nt < NTW; nt++) {
        int col = wid * NTW * 8 + nt * 8 + tig * 2;
        float b0 = __ldg(&bias[col]), b1 = __ldg(&bias[col + 1]);
        #pragma unroll
        for (int mt = 0; mt < 4; mt++) {
            long long r0 = mbase + mt * 16 + gid;
            long long r1 = r0 + 8;
            if (r0 < n) {
                float2 v;
                v.x = fmaxf(acc[mt][nt][0] + b0, 0.f);
                v.y = fmaxf(acc[mt][nt][1] + b1, 0.f);
                *(float2*)(out + r0 * N + col) = v;
            }
            if (r1 < n) {
                float2 v;
                v.x = fmaxf(acc[mt][nt][2] + b0, 0.f);
                v.y = fmaxf(acc[mt][nt][3] + b1, 0.f);
                *(float2*)(out + r1 * N + col) = v;
            }
        }
    }
}

// ---------------- last dist column (vs out2 row n2-1) ----------------
__global__ void lastcol_kernel(const float* __restrict__ o1, const float* __restrict__ o2,
                               float* __restrict__ lastc, int n, int n2) {
    __shared__ float b[64];
    if (threadIdx.x < 64) b[threadIdx.x] = o2[(n2 - 1) * 64 + threadIdx.x];
    __syncthreads();
    int w = (blockIdx.x * blockDim.x + threadIdx.x) >> 5;
    int lane = threadIdx.x & 31;
    if (w >= n) return;
    float t0 = o1[(long long)w * 64 + lane] - b[lane];
    float t1 = o1[(long long)w * 64 + 32 + lane] - b[32 + lane];
    float d = t0 * t0 + t1 * t1;
    for (int off = 16; off; off >>= 1) d += __shfl_xor_sync(0xffffffffu, d, off);
    if (lane == 0) lastc[w] = sqrtf(fmaxf(d, 0.f));
}

// ---------------- top-K: per-chunk bitonic (exact), then merge ----------------
__global__ void topk_part_kernel(const float* __restrict__ lastc, u64* __restrict__ pk,
                                 int npg, int ch) {
    __shared__ u64 key[1024];
    int g = blockIdx.x >> 3, c = blockIdx.x & 7;
    int base = c * ch;
    for (int i = threadIdx.x; i < 1024; i += blockDim.x) {
        int li = base + i;
        u64 k = 0xFFFFFFFFFFFFFFFFull;
        if (i < ch && li < npg) {
            unsigned u = __float_as_uint(lastc[g * npg + li]);
            u = (u & 0x80000000u) ? ~u : (u | 0x80000000u);
            u = ~u;
            k = ((u64)u << 32) | (unsigned)li;
        }
        key[i] = k;
    }
    __syncthreads();
    for (int size = 2; size <= 1024; size <<= 1) {
        for (int stride = size >> 1; stride > 0; stride >>= 1) {
            for (int i = threadIdx.x; i < 1024; i += blockDim.x) {
                int j = i ^ stride;
                if (j > i) {
                    u64 a = key[i], b = key[j];
                    bool up = ((i & size) == 0);
                    if ((a > b) == up) { key[i] = b; key[j] = a; }
                }
            }
            __syncthreads();
        }
    }
    if (threadIdx.x < KSEL) pk[(g * 8 + c) * KSEL + threadIdx.x] = key[threadIdx.x];
}

__global__ void topk_merge_kernel(const u64* __restrict__ pk, int* __restrict__ topk, int npg) {
    __shared__ u64 key[512];
    int g = blockIdx.x;
    for (int i = threadIdx.x; i < 512; i += blockDim.x)
        key[i] = (i < 8 * KSEL) ? pk[g * 8 * KSEL + i] : 0xFFFFFFFFFFFFFFFFull;
    __syncthreads();
    for (int size = 2; size <= 512; size <<= 1) {
        for (int stride = size >> 1; stride > 0; stride >>= 1) {
            for (int i = threadIdx.x; i < 512; i += blockDim.x) {
                int j = i ^ stride;
                if (j > i) {
                    u64 a = key[i], b = key[j];
                    bool up = ((i & size) == 0);
                    if ((a > b) == up) { key[i] = b; key[j] = a; }
                }
            }
            __syncthreads();
        }
    }
    if (threadIdx.x < KSEL)
        topk[g * KSEL + threadIdx.x] = g * npg + (int)(key[threadIdx.x] & 0xFFFFFFFFull);
}

// ---------------- full dist rows only for the B*K selected nodes ----------------
__global__ void feat_kernel(const float* __restrict__ o1, const float* __restrict__ o2,
                            const int* __restrict__ topk, float* __restrict__ feat, int n2) {
    __shared__ float a[64];
    int s = blockIdx.x;
    int node = topk[s];
    if (threadIdx.x < 64) a[threadIdx.x] = o1[(long long)node * 64 + threadIdx.x];
    __syncthreads();
    for (int j = threadIdx.x; j < n2; j += blockDim.x) {
        float d = 0.f;
        #pragma unroll
        for (int f = 0; f < 64; f++) {
            float t = a[f] - o2[j * 64 + f];
            d += t * t;
        }
        feat[s * n2 + j] = sqrtf(fmaxf(d, 0.f));
    }
}

// ---------------- fc1 ----------------
__global__ void fc1_kernel(const float* __restrict__ feat, const float* __restrict__ w,
                           const float* __restrict__ bias, float* __restrict__ z, int indim) {
    int b = blockIdx.x >> 7, o = blockIdx.x & 127;
    const float* fr = feat + (long long)b * indim;
    const float* wr = w + (long long)o * indim;
    float acc = 0.f;
    for (int i = threadIdx.x; i < indim; i += blockDim.x) acc += fr[i] * wr[i];
    __shared__ float red[256];
    red[threadIdx.x] = acc;
    __syncthreads();
    for (int s = 128; s > 0; s >>= 1) {
        if (threadIdx.x < s) red[threadIdx.x] += red[threadIdx.x + s];
        __syncthreads();
    }
    if (threadIdx.x == 0) z[b * 128 + o] = red[0] + bias[o];
}

// ---------------- layernorm + relu ----------------
__global__ void ln_relu_kernel(const float* __restrict__ z, const float* __restrict__ g,
                               const float* __restrict__ b, float* __restrict__ y, int F) {
    int bb = blockIdx.x, t = threadIdx.x;
    __shared__ float s[128];
    float v = z[bb * F + t];
    s[t] = v;
    __syncthreads();
    for (int st = F >> 1; st > 0; st >>= 1) { if (t < st) s[t] += s[t + st]; __syncthreads(); }
    float mu = s[0] / (float)F;
    __syncthreads();
    float d = v - mu;
    s[t] = d * d;
    __syncthreads();
    for (int st = F >> 1; st > 0; st >>= 1) { if (t < st) s[t] += s[t + st]; __syncthreads(); }
    float var = s[0] / (float)F;
    y[bb * F + t] = fmaxf(d * rsqrtf(var + 1e-5f) * g[t] + b[t], 0.f);
}

// ---------------- fc2 + LN + relu + fc3 + sigmoid ----------------
__global__ void head_kernel(const float* __restrict__ y1, const float* __restrict__ w2,
                            const float* __restrict__ b2, const float* __restrict__ g2,
                            const float* __restrict__ bn2, const float* __restrict__ w3,
                            const float* __restrict__ b3, float* __restrict__ out) {
    int b = blockIdx.x, t = threadIdx.x;  // 64 threads
    __shared__ float yr[128];
    yr[t] = y1[b * 128 + t];
    yr[64 + t] = y1[b * 128 + 64 + t];
    __syncthreads();
    float acc = b2[t];
    #pragma unroll 4
    for (int f = 0; f < 128; f++) acc += yr[f] * w2[t * 128 + f];
    __shared__ float s1[64], s2[64];
    s1[t] = acc;
    __syncthreads();
    for (int s = 32; s > 0; s >>= 1) { if (t < s) s1[t] += s1[t + s]; __syncthreads(); }
    float mu = s1[0] / 64.f;
    __syncthreads();
    float d = acc - mu;
    s2[t] = d * d;
    __syncthreads();
    for (int s = 32; s > 0; s >>= 1) { if (t < s) s2[t] += s2[t + s]; __syncthreads(); }
    float var = s2[0] / 64.f;
    float v = fmaxf(d * rsqrtf(var + 1e-5f) * g2[t] + bn2[t], 0.f);
    __syncthreads();
    s1[t] = v * w3[t];
    __syncthreads();
    for (int s = 32; s > 0; s >>= 1) { if (t < s) s1[t] += s1[t + s]; __syncthreads(); }
    if (t == 0) out[b] = 1.f / (1.f + expf(-(s1[0] + b3[0])));
}

// ---------------- launch ----------------
extern "C" void kernel_launch(void* const* d_in, const int* in_sizes, int n_in,
                              void* d_out, int out_size) {
    const float* x1   = (const float*)d_in[0];
    const int*   ei1  = (const int*)d_in[1];
    const float* x2   = (const float*)d_in[3];
    const int*   ei2  = (const int*)d_in[4];
    const float* w1l  = (const float*)d_in[5];
    const float* b1l  = (const float*)d_in[6];
    const float* w1r  = (const float*)d_in[7];
    const float* w2l  = (const float*)d_in[8];
    const float* b2l  = (const float*)d_in[9];
    const float* w2r  = (const float*)d_in[10];
    const float* fc1w = (const float*)d_in[11];
    const float* fc1b = (const float*)d_in[12];
    const float* ln1g = (const float*)d_in[13];
    const float* ln1b = (const float*)d_in[14];
    const float* fc2w = (const float*)d_in[15];
    const float* fc2b = (const float*)d_in[16];
    const float* ln2g = (const float*)d_in[17];
    const float* ln2b = (const float*)d_in[18];
    const float* fc3w = (const float*)d_in[19];
    const float* fc3b = (const float*)d_in[20];
    float* out = (float*)d_out;

    int N1 = in_sizes[0] / FDIM;
    int E1 = in_sizes[1] / 2;
    int N2 = in_sizes[3] / FDIM;
    int E2 = in_sizes[4] / 2;
    int NPG = N1 / BGR;
    int INDIM = KSEL * N2;
    int CH = (NPG + 7) / 8;

    int *deg1, *wpos1, *rowptr1, *col1, *deg2, *wpos2, *rowptr2, *col2, *topk, *part1, *part2;
    float *mean1, *h1, *o1, *mean2, *h2, *o2, *lastc, *feat, *z1, *y1;
    u64 *pk;
    cudaGetSymbolAddress((void**)&deg1, g_deg1);
    cudaGetSymbolAddress((void**)&wpos1, g_wpos1);
    cudaGetSymbolAddress((void**)&rowptr1, g_rowptr1);
    cudaGetSymbolAddress((void**)&col1, g_col1);
    cudaGetSymbolAddress((void**)&deg2, g_deg2);
    cudaGetSymbolAddress((void**)&wpos2, g_wpos2);
    cudaGetSymbolAddress((void**)&rowptr2, g_rowptr2);
    cudaGetSymbolAddress((void**)&col2, g_col2);
    cudaGetSymbolAddress((void**)&part1, g_part1);
    cudaGetSymbolAddress((void**)&part2, g_part2);
    cudaGetSymbolAddress((void**)&pk, g_pk);
    cudaGetSymbolAddress((void**)&topk, g_topk);
    cudaGetSymbolAddress((void**)&mean1, g_mean1);
    cudaGetSymbolAddress((void**)&h1, g_h1);
    cudaGetSymbolAddress((void**)&o1, g_o1);
    cudaGetSymbolAddress((void**)&mean2, g_mean2);
    cudaGetSymbolAddress((void**)&h2, g_h2);
    cudaGetSymbolAddress((void**)&o2, g_o2);
    cudaGetSymbolAddress((void**)&lastc, g_lastcol);
    cudaGetSymbolAddress((void**)&feat, g_feat);
    cudaGetSymbolAddress((void**)&z1, g_z1);
    cudaGetSymbolAddress((void**)&y1, g_y1);

    // smem: N=128 -> (2048*2 + 128*32*2) u32 = 48KB ; N=64 -> 32KB
    const int GSM128 = (2048 * 2 + 128 * 32 * 2) * 4;  // 49152
    const int GSM64  = (2048 * 2 + 64 * 32 * 2) * 4;   // 32768
    cudaFuncSetAttribute(gemm_mma_kernel<4>, cudaFuncAttributeMaxDynamicSharedMemorySize, GSM128);
    cudaFuncSetAttribute(gemm_mma_kernel<2>, cudaFuncAttributeMaxDynamicSharedMemorySize, GSM64);

    int zmax = (N1 > N2 ? N1 : N2);
    int nb1 = (N1 + 1023) / 1024, nb2 = (N2 + 1023) / 1024;
    zero_counts_kernel<<<(zmax + 255) / 256, 256>>>(N1, N2);
    degree_kernel<<<(E1 + 255) / 256, 256>>>(ei1, E1, deg1);
    degree_kernel<<<(E2 + 255) / 256, 256>>>(ei2, E2, deg2);
    block_sum_kernel<<<nb1, 256>>>(deg1, N1, part1);
    block_sum_kernel<<<nb2, 256>>>(deg2, N2, part2);
    scan_part_kernel<<<1, 128>>>(part1, nb1, rowptr1, N1);
    scan_part_kernel<<<1, 128>>>(part2, nb2, rowptr2, N2);
    write_rowptr_kernel<<<nb1, 1024>>>(deg1, N1, part1, rowptr1);
    write_rowptr_kernel<<<nb2, 1024>>>(deg2, N2, part2, rowptr2);
    scatter_kernel<<<(E1 + 255) / 256, 256>>>(ei1, E1, rowptr1, wpos1, col1);
    scatter_kernel<<<(E2 + 255) / 256, 256>>>(ei2, E2, rowptr2, wpos2, col2);

    int tiles1 = (N1 + 63) / 64;
    int tiles2 = (N2 + 63) / 64;

    // graph1 GNN
    aggregate_kernel<<<(N1 * 32 + 255) / 256, 256>>>(x1, rowptr1, col1, mean1, N1);
    gemm_mma_kernel<4><<<tiles1, 128, GSM128>>>(mean1, x1, w1l, w1r, b1l, h1, N1);
    aggregate_kernel<<<(N1 * 32 + 255) / 256, 256>>>(h1, rowptr1, col1, mean1, N1);
    gemm_mma_kernel<2><<<tiles1, 128, GSM64>>>(mean1, h1, w2l, w2r, b2l, o1, N1);

    // graph2 GNN (tiny)
    aggregate_kernel<<<(N2 * 32 + 255) / 256, 256>>>(x2, rowptr2, col2, mean2, N2);
    gemm_mma_kernel<4><<<tiles2, 128, GSM128>>>(mean2, x2, w1l, w1r, b1l, h2, N2);
    aggregate_kernel<<<(N2 * 32 + 255) / 256, 256>>>(h2, rowptr2, col2, mean2, N2);
    gemm_mma_kernel<2><<<tiles2, 128, GSM64>>>(mean2, h2, w2l, w2r, b2l, o2, N2);

    // ranking + selected features
    lastcol_kernel<<<(N1 * 32 + 255) / 256, 256>>>(o1, o2, lastc, N1, N2);
    topk_part_kernel<<<BGR * 8, 512>>>(lastc, pk, NPG, CH);
    topk_merge_kernel<<<BGR, 512>>>(pk, topk, NPG);
    feat_kernel<<<BGR * KSEL, 256>>>(o1, o2, topk, feat, N2);

    // MLP head
    fc1_kernel<<<BGR * 128, 256>>>(feat, fc1w, fc1b, z1, INDIM);
    ln_relu_kernel<<<BGR, 128>>>(z1, ln1g, ln1b, y1, 128);
    head_kernel<<<BGR, 64>>>(y1, fc2w, fc2b, ln2g, ln2b, fc3w, fc3b, out);
}

// round 7
// speedup vs baseline: 1.2467x; 1.2467x over previous
#include <cuda_runtime.h>
#include <math.h>
#include <stdint.h>

#define N1CAP 50000
#define E1CAP 1000000
#define N2CAP 256
#define E2CAP 4096
#define FDIM 128
#define BGR 10
#define KSEL 50
#define NN2 199
#define T16MAX 3136

typedef unsigned long long u64;

// ---------------- scratch (device globals; no allocation allowed) ----------------
__device__ int   g_deg1[N1CAP], g_wpos1[N1CAP], g_rowptr1[N1CAP + 1];
__device__ int   g_col1[E1CAP];
__device__ int   g_deg2[N2CAP], g_wpos2[N2CAP], g_rowptr2[N2CAP + 1];
__device__ int   g_col2[E2CAP];
__device__ int   g_part1[128], g_part2[128];
__device__ uint32_t g_fAh[(size_t)T16MAX * 2048];   // A fragments hi (25.7MB)
__device__ uint32_t g_fAl[(size_t)T16MAX * 2048];   // A fragments lo
__device__ uint32_t g_w1h[32 * 16 * 64], g_w1l[32 * 16 * 64];  // layer1 W frags (N=256)
__device__ uint32_t g_w2h[16 * 16 * 64], g_w2l[16 * 16 * 64];  // layer2 W frags (N=128)
__device__ float g_pq1[(size_t)N1CAP * 256];
__device__ float g_pq2[(size_t)N1CAP * 128];
__device__ float g_meanp1[(size_t)N1CAP * FDIM];
__device__ float g_meanp2[(size_t)N1CAP * 64];
__device__ float g_h1[(size_t)N1CAP * FDIM];
__device__ float g_o1[(size_t)N1CAP * 64];
__device__ float g_h2[N2CAP * FDIM];
__device__ float g_o2[N2CAP * 64];
__device__ float g_lastcol[N1CAP];
__device__ u64   g_pk[BGR * 8 * KSEL];
__device__ int   g_topk[BGR * KSEL];
__device__ float g_feat[BGR * KSEL * NN2];
__device__ float g_z1[BGR * FDIM];
__device__ float g_y1[BGR * FDIM];

// ---------------- CSR build ----------------
__global__ void zero_counts_kernel(int n1, int n2) {
    int i = blockIdx.x * blockDim.x + threadIdx.x;
    if (i < n1) { g_deg1[i] = 0; g_wpos1[i] = 0; }
    if (i < n2) { g_deg2[i] = 0; g_wpos2[i] = 0; }
}

__global__ void degree_kernel(const int* __restrict__ ei, int E, int* __restrict__ deg) {
    int e = blockIdx.x * blockDim.x + threadIdx.x;
    if (e < E) atomicAdd(&deg[ei[E + e]], 1);
}

__global__ void block_sum_kernel(const int* __restrict__ deg, int n, int* __restrict__ part) {
    __shared__ int s[256];
    int b = blockIdx.x;
    int base = b * 1024;
    int sum = 0;
    for (int i = threadIdx.x; i < 1024; i += 256) {
        int gi = base + i;
        if (gi < n) sum += deg[gi];
    }
    s[threadIdx.x] = sum;
    __syncthreads();
    for (int st = 128; st > 0; st >>= 1) {
        if (threadIdx.x < st) s[threadIdx.x] += s[threadIdx.x + st];
        __syncthreads();
    }
    if (threadIdx.x == 0) part[b] = s[0];
}

__global__ void scan_part_kernel(int* __restrict__ part, int nb, int* __restrict__ rowptr, int n) {
    __shared__ int s[128];
    int t = threadIdx.x;
    int v = (t < nb) ? part[t] : 0;
    s[t] = v;
    __syncthreads();
    for (int off = 1; off < 128; off <<= 1) {
        int u = (t >= off) ? s[t - off] : 0;
        __syncthreads();
        s[t] += u;
        __syncthreads();
    }
    if (t < nb) part[t] = s[t] - v;
    if (t == 127) rowptr[n] = s[127];
}

__global__ void write_rowptr_kernel(const int* __restrict__ deg, int n,
                                    const int* __restrict__ part, int* __restrict__ rowptr) {
    __shared__ int s[1024];
    int b = blockIdx.x, t = threadIdx.x;
    int gi = b * 1024 + t;
    int v = (gi < n) ? deg[gi] : 0;
    s[t] = v;
    __syncthreads();
    for (int off = 1; off < 1024; off <<= 1) {
        int u = (t >= off) ? s[t - off] : 0;
        __syncthreads();
        s[t] += u;
        __syncthreads();
    }
    if (gi < n) rowptr[gi] = part[b] + s[t] - v;
}

__global__ void scatter_kernel(const int* __restrict__ ei, int E,
                               const int* __restrict__ rowptr, int* __restrict__ wpos,
                               int* __restrict__ col) {
    int e = blockIdx.x * blockDim.x + threadIdx.x;
    if (e >= E) return;
    int d = ei[E + e];
    int p = atomicAdd(&wpos[d], 1);
    col[rowptr[d] + p] = ei[e];
}

// ---------------- tf32 helpers ----------------
__device__ __forceinline__ void tf32split(float v, uint32_t& hi, uint32_t& lo) {
    asm("cvt.rna.tf32.f32 %0, %1;" : "=r"(hi) : "f"(v));
    float l = v - __uint_as_float(hi);
    asm("cvt.rna.tf32.f32 %0, %1;" : "=r"(lo) : "f"(l));
}

#define MMA_TF32(ac, a, b0v, b1v) \
    asm volatile("mma.sync.aligned.m16n8k8.row.col.f32.tf32.tf32.f32 " \
                 "{%0,%1,%2,%3}, {%4,%5,%6,%7}, {%8,%9}, {%0,%1,%2,%3};" \
                 : "+f"((ac)[0]), "+f"((ac)[1]), "+f"((ac)[2]), "+f"((ac)[3]) \
                 : "r"((a)[0]), "r"((a)[1]), "r"((a)[2]), "r"((a)[3]), \
                   "r"(b0v), "r"(b1v))

// ---------------- convert A [n x 128] row-major -> fragment-order hi/lo ----------------
// layout: [T16][k8(16)][lane(32)][slot(4)], slots: (gid,tig),(gid+8,tig),(gid,tig+4),(gid+8,tig+4)
__global__ void convA_kernel(const float* __restrict__ src, int n, int t16tot,
                             uint32_t* __restrict__ dh, uint32_t* __restrict__ dl) {
    int widx = threadIdx.x >> 5, lane = threadIdx.x & 31;
    int T = blockIdx.x * 8 + widx;
    if (T >= t16tot) return;
    int gid = lane >> 2, tig = lane & 3;
    long long r0 = (long long)T * 16 + gid, r1 = r0 + 8;
    bool ok0 = r0 < n, ok1 = r1 < n;
    for (int k8 = 0; k8 < 16; k8++) {
        int c0 = k8 * 8 + tig, c1 = c0 + 4;
        float v00 = ok0 ? src[r0 * 128 + c0] : 0.f;
        float v01 = ok0 ? src[r0 * 128 + c1] : 0.f;
        float v10 = ok1 ? src[r1 * 128 + c0] : 0.f;
        float v11 = ok1 ? src[r1 * 128 + c1] : 0.f;
        uint4 h, l;
        tf32split(v00, h.x, l.x);
        tf32split(v10, h.y, l.y);
        tf32split(v01, h.z, l.z);
        tf32split(v11, h.w, l.w);
        size_t idx = ((size_t)T * 16 + k8) * 128 + lane * 4;
        *(uint4*)(dh + idx) = h;
        *(uint4*)(dl + idx) = l;
    }
}

// ---------------- convert stacked weights [Wa;Wb] -> fragment-order hi/lo ----------------
// layout: [nt][k8(16)][lane(32)][slot(2)], slots: (k=tig,n=gid),(k=tig+4,n=gid)
__global__ void convW_kernel(const float* __restrict__ Wa, const float* __restrict__ Wb,
                             int Nhalf, uint32_t* __restrict__ dh, uint32_t* __restrict__ dl) {
    int widx = threadIdx.x >> 5, lane = threadIdx.x & 31;
    int nt = blockIdx.x * 4 + widx;
    int ntTot = (2 * Nhalf) / 8;
    if (nt >= ntTot) return;
    int gid = lane >> 2, tig = lane & 3;
    int o = nt * 8 + gid;
    const float* Wrow = (o < Nhalf) ? (Wa + (size_t)o * 128) : (Wb + (size_t)(o - Nhalf) * 128);
    for (int k8 = 0; k8 < 16; k8++) {
        float v0 = Wrow[k8 * 8 + tig];
        float v1 = Wrow[k8 * 8 + tig + 4];
        uint2 h, l;
        tf32split(v0, h.x, l.x);
        tf32split(v1, h.y, l.y);
        size_t idx = ((size_t)nt * 16 + k8) * 64 + lane * 2;
        *(uint2*)(dh + idx) = h;
        *(uint2*)(dl + idx) = l;
    }
}

// ---------------- GEMM: out[m, o] = sum_k A[m,k] W[o,k], 3xTF32, no smem ----------------
template <int WARPS, int NTW>
__global__ void __launch_bounds__(WARPS * 32)
gemm_frag_kernel(const uint32_t* __restrict__ Ah, const uint32_t* __restrict__ Al,
                 const uint32_t* __restrict__ Bh, const uint32_t* __restrict__ Bl,
                 float* __restrict__ out, int n) {
    constexpr int N = WARPS * NTW * 8;
    int tid = threadIdx.x, wid = tid >> 5, lane = tid & 31;
    int gid = lane >> 2, tig = lane & 3;
    long long mbase = (long long)blockIdx.x * 64;
    int T0 = blockIdx.x * 4;

    float acc[4][NTW][4];
    #pragma unroll
    for (int mt = 0; mt < 4; mt++)
        #pragma unroll
        for (int nt = 0; nt < NTW; nt++)
            #pragma unroll
            for (int j = 0; j < 4; j++) acc[mt][nt][j] = 0.f;

    for (int k8 = 0; k8 < 16; k8++) {
        uint32_t ah[4][4], al[4][4];
        #pragma unroll
        for (int mt = 0; mt < 4; mt++) {
            size_t ai = ((size_t)(T0 + mt) * 16 + k8) * 128 + lane * 4;
            uint4 h = *(const uint4*)(Ah + ai);
            uint4 l = *(const uint4*)(Al + ai);
            ah[mt][0] = h.x; ah[mt][1] = h.y; ah[mt][2] = h.z; ah[mt][3] = h.w;
            al[mt][0] = l.x; al[mt][1] = l.y; al[mt][2] = l.z; al[mt][3] = l.w;
        }
        #pragma unroll
        for (int nt = 0; nt < NTW; nt++) {
            int gnt = wid * NTW + nt;
            size_t bi = ((size_t)gnt * 16 + k8) * 64 + lane * 2;
            uint2 bh = *(const uint2*)(Bh + bi);
            uint2 bl2 = *(const uint2*)(Bl + bi);
            #pragma unroll
            for (int mt = 0; mt < 4; mt++) {
                MMA_TF32(acc[mt][nt], ah[mt], bh.x, bh.y);
                MMA_TF32(acc[mt][nt], ah[mt], bl2.x, bl2.y);
                MMA_TF32(acc[mt][nt], al[mt], bh.x, bh.y);
            }
        }
    }

    #pragma unroll
    for (int nt = 0; nt < NTW; nt++) {
        int col = wid * NTW * 8 + nt * 8 + tig * 2;
        #pragma unroll
        for (int mt = 0; mt < 4; mt++) {
            long long r0 = mbase + mt * 16 + gid;
            long long r1 = r0 + 8;
            if (r0 < n) {
                float2 v = {acc[mt][nt][0], acc[mt][nt][1]};
                *(float2*)(out + r0 * N + col) = v;
            }
            if (r1 < n) {
                float2 v = {acc[mt][nt][2], acc[mt][nt][3]};
                *(float2*)(out + r1 * N + col) = v;
            }
        }
    }
}

// ---------------- mean aggregation over first GROUP*4 cols of src rows ----------------
template <int GROUP>
__global__ void agg_kernel(const float* __restrict__ src, int srcStride4,
                           const int* __restrict__ rowptr, const int* __restrict__ col,
                           float* __restrict__ dst, int n) {
    int gt = blockIdx.x * blockDim.x + threadIdx.x;
    int w = gt >> 5, lane = gt & 31;
    constexpr int NP = 32 / GROUP;
    int node = w * NP + lane / GROUP;
    int li = lane % GROUP;
    if (node >= n) return;
    int s = rowptr[node], e = rowptr[node + 1];
    const float4* s4 = (const float4*)src;
    float4 acc = make_float4(0.f, 0.f, 0.f, 0.f);
    #pragma unroll 4
    for (int j = s; j < e; j++) {
        float4 v = s4[(long long)col[j] * srcStride4 + li];
        acc.x += v.x; acc.y += v.y; acc.z += v.z; acc.w += v.w;
    }
    float inv = 1.0f / (float)max(e - s, 1);
    acc.x *= inv; acc.y *= inv; acc.z *= inv; acc.w *= inv;
    ((float4*)dst)[(long long)node * GROUP + li] = acc;
}

// ---------------- combine layer1: h = relu(meanp + b + q) ----------------
__global__ void combine1_kernel(const float* __restrict__ meanp, const float* __restrict__ pq,
                                const float* __restrict__ bias, float* __restrict__ h,
                                int n) {
    long long i = (long long)blockIdx.x * blockDim.x + threadIdx.x;
    if (i >= (long long)n * 32) return;
    long long m = i >> 5;
    int f = (int)(i & 31);
    float4 a = ((const float4*)meanp)[i];
    float4 q = ((const float4*)pq)[m * 64 + 32 + f];
    float4 b = ((const float4*)bias)[f];
    float4 r;
    r.x = fmaxf(a.x + q.x + b.x, 0.f);
    r.y = fmaxf(a.y + q.y + b.y, 0.f);
    r.z = fmaxf(a.z + q.z + b.z, 0.f);
    r.w = fmaxf(a.w + q.w + b.w, 0.f);
    ((float4*)h)[i] = r;
}

// ---------------- combine layer2 (+ optional fused lastcol) ----------------
__global__ void combine2_kernel(const float* __restrict__ meanp2, const float* __restrict__ pq2,
                                const float* __restrict__ bias, float* __restrict__ o,
                                const float* __restrict__ o2last, float* __restrict__ lastc,
                                int n) {
    __shared__ float bl[64];
    if (o2last != nullptr && threadIdx.x < 64) bl[threadIdx.x] = o2last[threadIdx.x];
    __syncthreads();
    int w = (blockIdx.x * blockDim.x + threadIdx.x) >> 5;
    int j = threadIdx.x & 31;
    if (w >= n) return;
    float a0 = fmaxf(meanp2[(long long)w * 64 + j] + bias[j]
                     + pq2[(long long)w * 128 + 64 + j], 0.f);
    float a1 = fmaxf(meanp2[(long long)w * 64 + 32 + j] + bias[32 + j]
                     + pq2[(long long)w * 128 + 96 + j], 0.f);
    o[(long long)w * 64 + j] = a0;
    o[(long long)w * 64 + 32 + j] = a1;
    if (lastc != nullptr) {
        float t0 = a0 - bl[j], t1 = a1 - bl[32 + j];
        float d = t0 * t0 + t1 * t1;
        for (int off = 16; off; off >>= 1) d += __shfl_xor_sync(0xffffffffu, d, off);
        if (j == 0) lastc[w] = sqrtf(fmaxf(d, 0.f));
    }
}

// ---------------- top-K: per-chunk bitonic (exact), then merge ----------------
__global__ void topk_part_kernel(const float* __restrict__ lastc, u64* __restrict__ pk,
                                 int npg, int ch) {
    __shared__ u64 key[1024];
    int g = blockIdx.x >> 3, c = blockIdx.x & 7;
    int base = c * ch;
    for (int i = threadIdx.x; i < 1024; i += blockDim.x) {
        int li = base + i;
        u64 k = 0xFFFFFFFFFFFFFFFFull;
        if (i < ch && li < npg) {
            unsigned u = __float_as_uint(lastc[g * npg + li]);
            u = (u & 0x80000000u) ? ~u : (u | 0x80000000u);
            u = ~u;
            k = ((u64)u << 32) | (unsigned)li;
        }
        key[i] = k;
    }
    __syncthreads();
    for (int size = 2; size <= 1024; size <<= 1) {
        for (int stride = size >> 1; stride > 0; stride >>= 1) {
            for (int i = threadIdx.x; i < 1024; i += blockDim.x) {
                int j = i ^ stride;
                if (j > i) {
                    u64 a = key[i], b = key[j];
                    bool up = ((i & size) == 0);
                    if ((a > b) == up) { key[i] = b; key[j] = a; }
                }
            }
            __syncthreads();
        }
    }
    if (threadIdx.x < KSEL) pk[(g * 8 + c) * KSEL + threadIdx.x] = key[threadIdx.x];
}

__global__ void topk_merge_kernel(const u64* __restrict__ pk, int* __restrict__ topk, int npg) {
    __shared__ u64 key[512];
    int g = blockIdx.x;
    for (int i = threadIdx.x; i < 512; i += blockDim.x)
        key[i] = (i < 8 * KSEL) ? pk[g * 8 * KSEL + i] : 0xFFFFFFFFFFFFFFFFull;
    __syncthreads();
    for (int size = 2; size <= 512; size <<= 1) {
        for (int stride = size >> 1; stride > 0; stride >>= 1) {
            for (int i = threadIdx.x; i < 512; i += blockDim.x) {
                int j = i ^ stride;
                if (j > i) {
                    u64 a = key[i], b = key[j];
                    bool up = ((i & size) == 0);
                    if ((a > b) == up) { key[i] = b; key[j] = a; }
                }
            }
            __syncthreads();
        }
    }
    if (threadIdx.x < KSEL)
        topk[g * KSEL + threadIdx.x] = g * npg + (int)(key[threadIdx.x] & 0xFFFFFFFFull);
}

// ---------------- full dist rows only for the B*K selected nodes ----------------
__global__ void feat_kernel(const float* __restrict__ o1, const float* __restrict__ o2,
                            const int* __restrict__ topk, float* __restrict__ feat, int n2) {
    __shared__ float a[64];
    int s = blockIdx.x;
    int node = topk[s];
    if (threadIdx.x < 64) a[threadIdx.x] = o1[(long long)node * 64 + threadIdx.x];
    __syncthreads();
    for (int j = threadIdx.x; j < n2; j += blockDim.x) {
        float d = 0.f;
        #pragma unroll
        for (int f = 0; f < 64; f++) {
            float t = a[f] - o2[j * 64 + f];
            d += t * t;
        }
        feat[s * n2 + j] = sqrtf(fmaxf(d, 0.f));
    }
}

// ---------------- fc1 ----------------
__global__ void fc1_kernel(const float* __restrict__ feat, const float* __restrict__ w,
                           const float* __restrict__ bias, float* __restrict__ z, int indim) {
    int b = blockIdx.x >> 7, o = blockIdx.x & 127;
    const float* fr = feat + (long long)b * indim;
    const float* wr = w + (long long)o * indim;
    float acc = 0.f;
    for (int i = threadIdx.x; i < indim; i += blockDim.x) acc += fr[i] * wr[i];
    __shared__ float red[256];
    red[threadIdx.x] = acc;
    __syncthreads();
    for (int s = 128; s > 0; s >>= 1) {
        if (threadIdx.x < s) red[threadIdx.x] += red[threadIdx.x + s];
        __syncthreads();
    }
    if (threadIdx.x == 0) z[b * 128 + o] = red[0] + bias[o];
}

// ---------------- layernorm + relu ----------------
__global__ void ln_relu_kernel(const float* __restrict__ z, const float* __restrict__ g,
                               const float* __restrict__ b, float* __restrict__ y, int F) {
    int bb = blockIdx.x, t = threadIdx.x;
    __shared__ float s[128];
    float v = z[bb * F + t];
    s[t] = v;
    __syncthreads();
    for (int st = F >> 1; st > 0; st >>= 1) { if (t < st) s[t] += s[t + st]; __syncthreads(); }
    float mu = s[0] / (float)F;
    __syncthreads();
    float d = v - mu;
    s[t] = d * d;
    __syncthreads();
    for (int st = F >> 1; st > 0; st >>= 1) { if (t < st) s[t] += s[t + st]; __syncthreads(); }
    float var = s[0] / (float)F;
    y[bb * F + t] = fmaxf(d * rsqrtf(var + 1e-5f) * g[t] + b[t], 0.f);
}

// ---------------- fc2 + LN + relu + fc3 + sigmoid ----------------
__global__ void head_kernel(const float* __restrict__ y1, const float* __restrict__ w2,
                            const float* __restrict__ b2, const float* __restrict__ g2,
                            const float* __restrict__ bn2, const float* __restrict__ w3,
                            const float* __restrict__ b3, float* __restrict__ out) {
    int b = blockIdx.x, t = threadIdx.x;  // 64 threads
    __shared__ float yr[128];
    yr[t] = y1[b * 128 + t];
    yr[64 + t] = y1[b * 128 + 64 + t];
    __syncthreads();
    float acc = b2[t];
    #pragma unroll 4
    for (int f = 0; f < 128; f++) acc += yr[f] * w2[t * 128 + f];
    __shared__ float s1[64], s2[64];
    s1[t] = acc;
    __syncthreads();
    for (int s = 32; s > 0; s >>= 1) { if (t < s) s1[t] += s1[t + s]; __syncthreads(); }
    float mu = s1[0] / 64.f;
    __syncthreads();
    float d = acc - mu;
    s2[t] = d * d;
    __syncthreads();
    for (int s = 32; s > 0; s >>= 1) { if (t < s) s2[t] += s2[t + s]; __syncthreads(); }
    float var = s2[0] / 64.f;
    float v = fmaxf(d * rsqrtf(var + 1e-5f) * g2[t] + bn2[t], 0.f);
    __syncthreads();
    s1[t] = v * w3[t];
    __syncthreads();
    for (int s = 32; s > 0; s >>= 1) { if (t < s) s1[t] += s1[t + s]; __syncthreads(); }
    if (t == 0) out[b] = 1.f / (1.f + expf(-(s1[0] + b3[0])));
}

// ---------------- launch ----------------
extern "C" void kernel_launch(void* const* d_in, const int* in_sizes, int n_in,
                              void* d_out, int out_size) {
    const float* x1   = (const float*)d_in[0];
    const int*   ei1  = (const int*)d_in[1];
    const float* x2   = (const float*)d_in[3];
    const int*   ei2  = (const int*)d_in[4];
    const float* w1l  = (const float*)d_in[5];
    const float* b1l  = (const float*)d_in[6];
    const float* w1r  = (const float*)d_in[7];
    const float* w2l  = (const float*)d_in[8];
    const float* b2l  = (const float*)d_in[9];
    const float* w2r  = (const float*)d_in[10];
    const float* fc1w = (const float*)d_in[11];
    const float* fc1b = (const float*)d_in[12];
    const float* ln1g = (const float*)d_in[13];
    const float* ln1b = (const float*)d_in[14];
    const float* fc2w = (const float*)d_in[15];
    const float* fc2b = (const float*)d_in[16];
    const float* ln2g = (const float*)d_in[17];
    const float* ln2b = (const float*)d_in[18];
    const float* fc3w = (const float*)d_in[19];
    const float* fc3b = (const float*)d_in[20];
    float* out = (float*)d_out;

    int N1 = in_sizes[0] / FDIM;
    int E1 = in_sizes[1] / 2;
    int N2 = in_sizes[3] / FDIM;
    int E2 = in_sizes[4] / 2;
    int NPG = N1 / BGR;
    int INDIM = KSEL * N2;
    int CH = (NPG + 7) / 8;

    int *deg1, *wpos1, *rowptr1, *col1, *deg2, *wpos2, *rowptr2, *col2, *topk, *part1, *part2;
    float *pq1, *pq2, *meanp1, *meanp2, *h1, *o1, *h2, *o2, *lastc, *feat, *z1, *y1;
    uint32_t *fAh, *fAl, *w1h, *w1lo, *w2h, *w2lo;
    u64 *pk;
    cudaGetSymbolAddress((void**)&deg1, g_deg1);
    cudaGetSymbolAddress((void**)&wpos1, g_wpos1);
    cudaGetSymbolAddress((void**)&rowptr1, g_rowptr1);
    cudaGetSymbolAddress((void**)&col1, g_col1);
    cudaGetSymbolAddress((void**)&deg2, g_deg2);
    cudaGetSymbolAddress((void**)&wpos2, g_wpos2);
    cudaGetSymbolAddress((void**)&rowptr2, g_rowptr2);
    cudaGetSymbolAddress((void**)&col2, g_col2);
    cudaGetSymbolAddress((void**)&part1, g_part1);
    cudaGetSymbolAddress((void**)&part2, g_part2);
    cudaGetSymbolAddress((void**)&fAh, g_fAh);
    cudaGetSymbolAddress((void**)&fAl, g_fAl);
    cudaGetSymbolAddress((void**)&w1h, g_w1h);
    cudaGetSymbolAddress((void**)&w1lo, g_w1l);
    cudaGetSymbolAddress((void**)&w2h, g_w2h);
    cudaGetSymbolAddress((void**)&w2lo, g_w2l);
    cudaGetSymbolAddress((void**)&pq1, g_pq1);
    cudaGetSymbolAddress((void**)&pq2, g_pq2);
    cudaGetSymbolAddress((void**)&meanp1, g_meanp1);
    cudaGetSymbolAddress((void**)&meanp2, g_meanp2);
    cudaGetSymbolAddress((void**)&h1, g_h1);
    cudaGetSymbolAddress((void**)&o1, g_o1);
    cudaGetSymbolAddress((void**)&h2, g_h2);
    cudaGetSymbolAddress((void**)&o2, g_o2);
    cudaGetSymbolAddress((void**)&lastc, g_lastcol);
    cudaGetSymbolAddress((void**)&pk, g_pk);
    cudaGetSymbolAddress((void**)&topk, g_topk);
    cudaGetSymbolAddress((void**)&feat, g_feat);
    cudaGetSymbolAddress((void**)&z1, g_z1);
    cudaGetSymbolAddress((void**)&y1, g_y1);

    // ---- CSR build ----
    int zmax = (N1 > N2 ? N1 : N2);
    int nb1 = (N1 + 1023) / 1024, nb2 = (N2 + 1023) / 1024;
    zero_counts_kernel<<<(zmax + 255) / 256, 256>>>(N1, N2);
    degree_kernel<<<(E1 + 255) / 256, 256>>>(ei1, E1, deg1);
    degree_kernel<<<(E2 + 255) / 256, 256>>>(ei2, E2, deg2);
    block_sum_kernel<<<nb1, 256>>>(deg1, N1, part1);
    block_sum_kernel<<<nb2, 256>>>(deg2, N2, part2);
    scan_part_kernel<<<1, 128>>>(part1, nb1, rowptr1, N1);
    scan_part_kernel<<<1, 128>>>(part2, nb2, rowptr2, N2);
    write_rowptr_kernel<<<nb1, 1024>>>(deg1, N1, part1, rowptr1);
    write_rowptr_kernel<<<nb2, 1024>>>(deg2, N2, part2, rowptr2);
    scatter_kernel<<<(E1 + 255) / 256, 256>>>(ei1, E1, rowptr1, wpos1, col1);
    scatter_kernel<<<(E2 + 255) / 256, 256>>>(ei2, E2, rowptr2, wpos2, col2);

    // ---- weight fragment conversion ----
    convW_kernel<<<8, 128>>>(w1l, w1r, 128, w1h, w1lo);   // stacked N=256
    convW_kernel<<<4, 128>>>(w2l, w2r, 64, w2h, w2lo);    // stacked N=128

    int tiles1 = (N1 + 63) / 64, t16_1 = tiles1 * 4;
    int tiles2 = (N2 + 63) / 64, t16_2 = tiles2 * 4;

    // ---- graph2 (tiny) first: o2 needed for graph1's fused lastcol ----
    convA_kernel<<<(t16_2 + 7) / 8, 256>>>(x2, N2, t16_2, fAh, fAl);
    gemm_frag_kernel<8, 4><<<tiles2, 256>>>(fAh, fAl, w1h, w1lo, pq1, N2);
    agg_kernel<32><<<(N2 * 32 + 255) / 256, 256>>>(pq1, 64, rowptr2, col2, meanp1, N2);
    combine1_kernel<<<(N2 * 32 + 255) / 256, 256>>>(meanp1, pq1, b1l, h2, N2);
    convA_kernel<<<(t16_2 + 7) / 8, 256>>>(h2, N2, t16_2, fAh, fAl);
    gemm_frag_kernel<4, 4><<<tiles2, 128>>>(fAh, fAl, w2h, w2lo, pq2, N2);
    agg_kernel<16><<<(((N2 + 1) / 2) * 32 + 255) / 256, 256>>>(pq2, 32, rowptr2, col2, meanp2, N2);
    combine2_kernel<<<(N2 * 32 + 255) / 256, 256>>>(meanp2, pq2, b2l, o2, nullptr, nullptr, N2);

    // ---- graph1 ----
    convA_kernel<<<(t16_1 + 7) / 8, 256>>>(x1, N1, t16_1, fAh, fAl);
    gemm_frag_kernel<8, 4><<<tiles1, 256>>>(fAh, fAl, w1h, w1lo, pq1, N1);
    agg_kernel<32><<<(N1 * 32 + 255) / 256, 256>>>(pq1, 64, rowptr1, col1, meanp1, N1);
    combine1_kernel<<<(N1 * 32 + 255) / 256, 256>>>(meanp1, pq1, b1l, h1, N1);
    convA_kernel<<<(t16_1 + 7) / 8, 256>>>(h1, N1, t16_1, fAh, fAl);
    gemm_frag_kernel<4, 4><<<tiles1, 128>>>(fAh, fAl, w2h, w2lo, pq2, N1);
    agg_kernel<16><<<(((N1 + 1) / 2) * 32 + 255) / 256, 256>>>(pq2, 32, rowptr1, col1, meanp2, N1);
    combine2_kernel<<<(N1 * 32 + 255) / 256, 256>>>(meanp2, pq2, b2l, o1,
                                                    o2 + (size_t)(N2 - 1) * 64, lastc, N1);

    // ---- ranking + selected features + MLP head ----
    topk_part_kernel<<<BGR * 8, 512>>>(lastc, pk, NPG, CH);
    topk_merge_kernel<<<BGR, 512>>>(pk, topk, NPG);
    feat_kernel<<<BGR * KSEL, 256>>>(o1, o2, topk, feat, N2);
    fc1_kernel<<<BGR * 128, 256>>>(feat, fc1w, fc1b, z1, INDIM);
    ln_relu_kernel<<<BGR, 128>>>(z1, ln1g, ln1b, y1, 128);
    head_kernel<<<BGR, 64>>>(y1, fc2w, fc2b, ln2g, ln2b, fc3w, fc3b, out);
}

// round 9
// speedup vs baseline: 1.3346x; 1.0705x over previous
#include <cuda_runtime.h>
#include <math.h>
#include <stdint.h>

#define N1CAP 50000
#define E1CAP 1000000
#define N2CAP 256
#define E2CAP 4096
#define FDIM 128
#define BGR 10
#define KSEL 50
#define NN2 199
#define T16MAX 3136

typedef unsigned long long u64;

// ---------------- scratch (device globals; no allocation allowed) ----------------
__device__ int   g_deg1[N1CAP], g_wpos1[N1CAP], g_rowptr1[N1CAP + 1];
__device__ int   g_col1[E1CAP];
__device__ int   g_deg2[N2CAP], g_wpos2[N2CAP], g_rowptr2[N2CAP + 1];
__device__ int   g_col2[E2CAP];
__device__ int   g_part1[128], g_part2[128];
__device__ uint32_t g_fAh[(size_t)T16MAX * 2048];   // graph1 A fragments hi
__device__ uint32_t g_fAl[(size_t)T16MAX * 2048];   // graph1 A fragments lo
__device__ uint32_t g_fBh[16 * 2048], g_fBl[16 * 2048];  // graph2 A fragments
__device__ uint32_t g_w1h[32 * 16 * 64], g_w1l[32 * 16 * 64];  // layer1 W frags (N=256)
__device__ uint32_t g_w2h[16 * 16 * 64], g_w2l[16 * 16 * 64];  // layer2 W frags (N=128)
__device__ float g_pq1[(size_t)N1CAP * 256];
__device__ float g_pq2[(size_t)N1CAP * 128];
__device__ float g_pq1b[256 * 256];
__device__ float g_pq2b[256 * 128];
__device__ float g_o1[(size_t)N1CAP * 64];
__device__ float g_o2[N2CAP * 64];
__device__ float g_lastcol[N1CAP];
__device__ u64   g_pk[BGR * 8 * KSEL];
__device__ int   g_topk[BGR * KSEL];
__device__ float g_feat[BGR * KSEL * NN2];
__device__ float g_z1[BGR * FDIM];
__device__ float g_y1[BGR * FDIM];

// ---------------- tf32 helpers ----------------
__device__ __forceinline__ void tf32split(float v, uint32_t& hi, uint32_t& lo) {
    asm("cvt.rna.tf32.f32 %0, %1;" : "=r"(hi) : "f"(v));
    float l = v - __uint_as_float(hi);
    asm("cvt.rna.tf32.f32 %0, %1;" : "=r"(lo) : "f"(l));
}

#define MMA_TF32(ac, a, b0v, b1v) \
    asm volatile("mma.sync.aligned.m16n8k8.row.col.f32.tf32.tf32.f32 " \
                 "{%0,%1,%2,%3}, {%4,%5,%6,%7}, {%8,%9}, {%0,%1,%2,%3};" \
                 : "+f"((ac)[0]), "+f"((ac)[1]), "+f"((ac)[2]), "+f"((ac)[3]) \
                 : "r"((a)[0]), "r"((a)[1]), "r"((a)[2]), "r"((a)[3]), \
                   "r"(b0v), "r"(b1v))

// ---------------- CSR build ----------------
__global__ void zero_counts_kernel(int n1, int n2) {
    int i = blockIdx.x * blockDim.x + threadIdx.x;
    if (i < n1) { g_deg1[i] = 0; g_wpos1[i] = 0; }
    if (i < n2) { g_deg2[i] = 0; g_wpos2[i] = 0; }
}

__global__ void degree2_kernel(const int* __restrict__ ei1, int E1,
                               const int* __restrict__ ei2, int E2) {
    int e = blockIdx.x * blockDim.x + threadIdx.x;
    if (e < E1) atomicAdd(&g_deg1[ei1[E1 + e]], 1);
    else if (e - E1 < E2) atomicAdd(&g_deg2[ei2[E2 + (e - E1)]], 1);
}

__global__ void block_sum_kernel(const int* __restrict__ deg, int n, int* __restrict__ part) {
    __shared__ int s[256];
    int b = blockIdx.x;
    int base = b * 1024;
    int sum = 0;
    for (int i = threadIdx.x; i < 1024; i += 256) {
        int gi = base + i;
        if (gi < n) sum += deg[gi];
    }
    s[threadIdx.x] = sum;
    __syncthreads();
    for (int st = 128; st > 0; st >>= 1) {
        if (threadIdx.x < st) s[threadIdx.x] += s[threadIdx.x + st];
        __syncthreads();
    }
    if (threadIdx.x == 0) part[b] = s[0];
}

__global__ void scan_part2_kernel(int* __restrict__ p1, int nb1, int* __restrict__ r1, int n1,
                                  int* __restrict__ p2, int nb2, int* __restrict__ r2, int n2) {
    __shared__ int s[128];
    int* part = blockIdx.x ? p2 : p1;
    int* rowptr = blockIdx.x ? r2 : r1;
    int nb = blockIdx.x ? nb2 : nb1;
    int n = blockIdx.x ? n2 : n1;
    int t = threadIdx.x;
    int v = (t < nb) ? part[t] : 0;
    s[t] = v;
    __syncthreads();
    for (int off = 1; off < 128; off <<= 1) {
        int u = (t >= off) ? s[t - off] : 0;
        __syncthreads();
        s[t] += u;
        __syncthreads();
    }
    if (t < nb) part[t] = s[t] - v;
    if (t == 127) rowptr[n] = s[127];
}

__global__ void write_rowptr_kernel(const int* __restrict__ deg, int n,
                                    const int* __restrict__ part, int* __restrict__ rowptr) {
    __shared__ int s[1024];
    int b = blockIdx.x, t = threadIdx.x;
    int gi = b * 1024 + t;
    int v = (gi < n) ? deg[gi] : 0;
    s[t] = v;
    __syncthreads();
    for (int off = 1; off < 1024; off <<= 1) {
        int u = (t >= off) ? s[t - off] : 0;
        __syncthreads();
        s[t] += u;
        __syncthreads();
    }
    if (gi < n) rowptr[gi] = part[b] + s[t] - v;
}

__global__ void scatter2_kernel(const int* __restrict__ ei1, int E1,
                                const int* __restrict__ ei2, int E2) {
    int e = blockIdx.x * blockDim.x + threadIdx.x;
    if (e < E1) {
        int d = ei1[E1 + e];
        int p = atomicAdd(&g_wpos1[d], 1);
        g_col1[g_rowptr1[d] + p] = ei1[e];
    } else if (e - E1 < E2) {
        int ee = e - E1;
        int d = ei2[E2 + ee];
        int p = atomicAdd(&g_wpos2[d], 1);
        g_col2[g_rowptr2[d] + p] = ei2[ee];
    }
}

// ---------------- convert A [n x 128] row-major -> fragment-order hi/lo ----------------
__global__ void convA_kernel(const float* __restrict__ src, int n, int t16tot,
                             uint32_t* __restrict__ dh, uint32_t* __restrict__ dl) {
    int widx = threadIdx.x >> 5, lane = threadIdx.x & 31;
    int T = blockIdx.x * 8 + widx;
    if (T >= t16tot) return;
    int gid = lane >> 2, tig = lane & 3;
    long long r0 = (long long)T * 16 + gid, r1 = r0 + 8;
    bool ok0 = r0 < n, ok1 = r1 < n;
    for (int k8 = 0; k8 < 16; k8++) {
        int c0 = k8 * 8 + tig, c1 = c0 + 4;
        float v00 = ok0 ? src[r0 * 128 + c0] : 0.f;
        float v01 = ok0 ? src[r0 * 128 + c1] : 0.f;
        float v10 = ok1 ? src[r1 * 128 + c0] : 0.f;
        float v11 = ok1 ? src[r1 * 128 + c1] : 0.f;
        uint4 h, l;
        tf32split(v00, h.x, l.x);
        tf32split(v10, h.y, l.y);
        tf32split(v01, h.z, l.z);
        tf32split(v11, h.w, l.w);
        size_t idx = ((size_t)T * 16 + k8) * 128 + lane * 4;
        *(uint4*)(dh + idx) = h;
        *(uint4*)(dl + idx) = l;
    }
}

// ---------------- convert stacked weights [Wa;Wb] -> fragment-order hi/lo ----------------
__global__ void convW_kernel(const float* __restrict__ Wa, const float* __restrict__ Wb,
                             int Nhalf, uint32_t* __restrict__ dh, uint32_t* __restrict__ dl) {
    int widx = threadIdx.x >> 5, lane = threadIdx.x & 31;
    int nt = blockIdx.x * 4 + widx;
    int ntTot = (2 * Nhalf) / 8;
    if (nt >= ntTot) return;
    int gid = lane >> 2, tig = lane & 3;
    int o = nt * 8 + gid;
    const float* Wrow = (o < Nhalf) ? (Wa + (size_t)o * 128) : (Wb + (size_t)(o - Nhalf) * 128);
    for (int k8 = 0; k8 < 16; k8++) {
        float v0 = Wrow[k8 * 8 + tig];
        float v1 = Wrow[k8 * 8 + tig + 4];
        uint2 h, l;
        tf32split(v0, h.x, l.x);
        tf32split(v1, h.y, l.y);
        size_t idx = ((size_t)nt * 16 + k8) * 64 + lane * 2;
        *(uint2*)(dh + idx) = h;
        *(uint2*)(dl + idx) = l;
    }
}

// ---------------- GEMM: out[m, o] = sum_k A[m,k] W[o,k], 3xTF32, no smem ----------------
template <int WARPS, int NTW>
__global__ void __launch_bounds__(WARPS * 32)
gemm_frag_kernel(const uint32_t* __restrict__ Ah, const uint32_t* __restrict__ Al,
                 const uint32_t* __restrict__ Bh, const uint32_t* __restrict__ Bl,
                 float* __restrict__ out, int n) {
    constexpr int N = WARPS * NTW * 8;
    int tid = threadIdx.x, wid = tid >> 5, lane = tid & 31;
    int gid = lane >> 2, tig = lane & 3;
    long long mbase = (long long)blockIdx.x * 64;
    int T0 = blockIdx.x * 4;

    float acc[4][NTW][4];
    #pragma unroll
    for (int mt = 0; mt < 4; mt++)
        #pragma unroll
        for (int nt = 0; nt < NTW; nt++)
            #pragma unroll
            for (int j = 0; j < 4; j++) acc[mt][nt][j] = 0.f;

    for (int k8 = 0; k8 < 16; k8++) {
        uint32_t ah[4][4], al[4][4];
        #pragma unroll
        for (int mt = 0; mt < 4; mt++) {
            size_t ai = ((size_t)(T0 + mt) * 16 + k8) * 128 + lane * 4;
            uint4 h = *(const uint4*)(Ah + ai);
            uint4 l = *(const uint4*)(Al + ai);
            ah[mt][0] = h.x; ah[mt][1] = h.y; ah[mt][2] = h.z; ah[mt][3] = h.w;
            al[mt][0] = l.x; al[mt][1] = l.y; al[mt][2] = l.z; al[mt][3] = l.w;
        }
        #pragma unroll
        for (int nt = 0; nt < NTW; nt++) {
            int gnt = wid * NTW + nt;
            size_t bi = ((size_t)gnt * 16 + k8) * 64 + lane * 2;
            uint2 bh = *(const uint2*)(Bh + bi);
            uint2 bl2 = *(const uint2*)(Bl + bi);
            #pragma unroll
            for (int mt = 0; mt < 4; mt++) {
                MMA_TF32(acc[mt][nt], ah[mt], bh.x, bh.y);
                MMA_TF32(acc[mt][nt], ah[mt], bl2.x, bl2.y);
                MMA_TF32(acc[mt][nt], al[mt], bh.x, bh.y);
            }
        }
    }

    #pragma unroll
    for (int nt = 0; nt < NTW; nt++) {
        int col = wid * NTW * 8 + nt * 8 + tig * 2;
        #pragma unroll
        for (int mt = 0; mt < 4; mt++) {
            long long r0 = mbase + mt * 16 + gid;
            long long r1 = r0 + 8;
            if (r0 < n) {
                float2 v = {acc[mt][nt][0], acc[mt][nt][1]};
                *(float2*)(out + r0 * N + col) = v;
            }
            if (r1 < n) {
                float2 v = {acc[mt][nt][2], acc[mt][nt][3]};
                *(float2*)(out + r1 * N + col) = v;
            }
        }
    }
}

// ---------------- fused layer1: agg(mean of pq[.,0:128]) + self + bias + relu -> fragments ----
// block = 512 thr = 16 warps = one T16 tile. smem tile padded 132 for conflict-free emit.
__global__ void __launch_bounds__(512)
fused_l1_kernel(const float* __restrict__ pq, const float* __restrict__ bias,
                const int* __restrict__ rowptr, const int* __restrict__ col,
                uint32_t* __restrict__ dh, uint32_t* __restrict__ dl, int n) {
    __shared__ float ht[16][132];
    int w = threadIdx.x >> 5, lane = threadIdx.x & 31;
    int T = blockIdx.x;
    int node = T * 16 + w;
    float4 r = make_float4(0.f, 0.f, 0.f, 0.f);
    if (node < n) {
        int s = rowptr[node], e = rowptr[node + 1];
        const float4* s4 = (const float4*)pq;
        float4 acc = make_float4(0.f, 0.f, 0.f, 0.f);
        #pragma unroll 4
        for (int j = s; j < e; j++) {
            float4 v = s4[(long long)col[j] * 64 + lane];
            acc.x += v.x; acc.y += v.y; acc.z += v.z; acc.w += v.w;
        }
        float inv = 1.0f / (float)max(e - s, 1);
        float4 q = s4[(long long)node * 64 + 32 + lane];
        float4 b = ((const float4*)bias)[lane];
        r.x = fmaxf(acc.x * inv + q.x + b.x, 0.f);
        r.y = fmaxf(acc.y * inv + q.y + b.y, 0.f);
        r.z = fmaxf(acc.z * inv + q.z + b.z, 0.f);
        r.w = fmaxf(acc.w * inv + q.w + b.w, 0.f);
    }
    ht[w][lane * 4] = r.x;
    ht[w][lane * 4 + 1] = r.y;
    ht[w][lane * 4 + 2] = r.z;
    ht[w][lane * 4 + 3] = r.w;
    __syncthreads();
    // emit fragments: warp w handles k8 = w (16 k8), lanes cover 32 positions
    int k8 = w;
    int gid = lane >> 2, tig = lane & 3;
    int c0 = k8 * 8 + tig, c1 = c0 + 4;
    float v00 = ht[gid][c0], v10 = ht[gid + 8][c0];
    float v01 = ht[gid][c1], v11 = ht[gid + 8][c1];
    uint4 h, l;
    tf32split(v00, h.x, l.x);
    tf32split(v10, h.y, l.y);
    tf32split(v01, h.z, l.z);
    tf32split(v11, h.w, l.w);
    size_t idx = ((size_t)T * 16 + k8) * 128 + lane * 4;
    *(uint4*)(dh + idx) = h;
    *(uint4*)(dl + idx) = l;
}

// ---------------- fused layer2: agg(mean of pq2[.,0:64]) + self + bias + relu -> o (+lastcol) --
__global__ void fused_l2_kernel(const float* __restrict__ pq2, const float* __restrict__ bias,
                                const int* __restrict__ rowptr, const int* __restrict__ col,
                                float* __restrict__ o, const float* __restrict__ o2last,
                                float* __restrict__ lastc, int n) {
    __shared__ float bl[64];
    if (o2last != nullptr && threadIdx.x < 64) bl[threadIdx.x] = o2last[threadIdx.x];
    __syncthreads();
    int gt = blockIdx.x * blockDim.x + threadIdx.x;
    int wrp = gt >> 5, lane = gt & 31;
    int node = wrp * 2 + (lane >> 4);
    int li = lane & 15;
    if (node >= n) return;
    int s = rowptr[node], e = rowptr[node + 1];
    const float4* s4 = (const float4*)pq2;
    float4 acc = make_float4(0.f, 0.f, 0.f, 0.f);
    #pragma unroll 4
    for (int j = s; j < e; j++) {
        float4 v = s4[(long long)col[j] * 32 + li];
        acc.x += v.x; acc.y += v.y; acc.z += v.z; acc.w += v.w;
    }
    float inv = 1.0f / (float)max(e - s, 1);
    float4 q = s4[(long long)node * 32 + 16 + li];
    float4 b = ((const float4*)bias)[li];
    float4 r;
    r.x = fmaxf(acc.x * inv + q.x + b.x, 0.f);
    r.y = fmaxf(acc.y * inv + q.y + b.y, 0.f);
    r.z = fmaxf(acc.z * inv + q.z + b.z, 0.f);
    r.w = fmaxf(acc.w * inv + q.w + b.w, 0.f);
    ((float4*)o)[(long long)node * 16 + li] = r;
    if (lastc != nullptr) {
        float4 blv = ((const float4*)bl)[li];
        float t0 = r.x - blv.x, t1 = r.y - blv.y, t2 = r.z - blv.z, t3 = r.w - blv.w;
        float d = t0 * t0 + t1 * t1 + t2 * t2 + t3 * t3;
        #pragma unroll
        for (int off = 8; off; off >>= 1) d += __shfl_xor_sync(0xffffffffu, d, off);
        if (li == 0) lastc[node] = sqrtf(fmaxf(d, 0.f));
    }
}

// ---------------- top-K: per-chunk bitonic (exact), then merge ----------------
__global__ void topk_part_kernel(const float* __restrict__ lastc, u64* __restrict__ pk,
                                 int npg, int ch) {
    __shared__ u64 key[1024];
    int g = blockIdx.x >> 3, c = blockIdx.x & 7;
    int base = c * ch;
    for (int i = threadIdx.x; i < 1024; i += blockDim.x) {
        int li = base + i;
        u64 k = 0xFFFFFFFFFFFFFFFFull;
        if (i < ch && li < npg) {
            unsigned u = __float_as_uint(lastc[g * npg + li]);
            u = (u & 0x80000000u) ? ~u : (u | 0x80000000u);
            u = ~u;
            k = ((u64)u << 32) | (unsigned)li;
        }
        key[i] = k;
    }
    __syncthreads();
    for (int size = 2; size <= 1024; size <<= 1) {
        for (int stride = size >> 1; stride > 0; stride >>= 1) {
            for (int i = threadIdx.x; i < 1024; i += blockDim.x) {
                int j = i ^ stride;
                if (j > i) {
                    u64 a = key[i], b = key[j];
                    bool up = ((i & size) == 0);
                    if ((a > b) == up) { key[i] = b; key[j] = a; }
                }
            }
            __syncthreads();
        }
    }
    if (threadIdx.x < KSEL) pk[(g * 8 + c) * KSEL + threadIdx.x] = key[threadIdx.x];
}

__global__ void topk_merge_kernel(const u64* __restrict__ pk, int* __restrict__ topk, int npg) {
    __shared__ u64 key[512];
    int g = blockIdx.x;
    for (int i = threadIdx.x; i < 512; i += blockDim.x)
        key[i] = (i < 8 * KSEL) ? pk[g * 8 * KSEL + i] : 0xFFFFFFFFFFFFFFFFull;
    __syncthreads();
    for (int size = 2; size <= 512; size <<= 1) {
        for (int stride = size >> 1; stride > 0; stride >>= 1) {
            for (int i = threadIdx.x; i < 512; i += blockDim.x) {
                int j = i ^ stride;
                if (j > i) {
                    u64 a = key[i], b = key[j];
                    bool up = ((i & size) == 0);
                    if ((a > b) == up) { key[i] = b; key[j] = a; }
                }
            }
            __syncthreads();
        }
    }
    if (threadIdx.x < KSEL)
        topk[g * KSEL + threadIdx.x] = g * npg + (int)(key[threadIdx.x] & 0xFFFFFFFFull);
}

// ---------------- full dist rows only for the B*K selected nodes ----------------
__global__ void feat_kernel(const float* __restrict__ o1, const float* __restrict__ o2,
                            const int* __restrict__ topk, float* __restrict__ feat, int n2) {
    __shared__ float a[64];
    int s = blockIdx.x;
    int node = topk[s];
    if (threadIdx.x < 64) a[threadIdx.x] = o1[(long long)node * 64 + threadIdx.x];
    __syncthreads();
    for (int j = threadIdx.x; j < n2; j += blockDim.x) {
        float d = 0.f;
        #pragma unroll
        for (int f = 0; f < 64; f++) {
            float t = a[f] - o2[j * 64 + f];
            d += t * t;
        }
        feat[s * n2 + j] = sqrtf(fmaxf(d, 0.f));
    }
}

// ---------------- fc1 ----------------
__global__ void fc1_kernel(const float* __restrict__ feat, const float* __restrict__ w,
                           const float* __restrict__ bias, float* __restrict__ z, int indim) {
    int b = blockIdx.x >> 7, o = blockIdx.x & 127;
    const float* fr = feat + (long long)b * indim;
    const float* wr = w + (long long)o * indim;
    float acc = 0.f;
    for (int i = threadIdx.x; i < indim; i += blockDim.x) acc += fr[i] * wr[i];
    __shared__ float red[256];
    red[threadIdx.x] = acc;
    __syncthreads();
    for (int s = 128; s > 0; s >>= 1) {
        if (threadIdx.x < s) red[threadIdx.x] += red[threadIdx.x + s];
        __syncthreads();
    }
    if (threadIdx.x == 0) z[b * 128 + o] = red[0] + bias[o];
}

// ---------------- layernorm + relu ----------------
__global__ void ln_relu_kernel(const float* __restrict__ z, const float* __restrict__ g,
                               const float* __restrict__ b, float* __restrict__ y, int F) {
    int bb = blockIdx.x, t = threadIdx.x;
    __shared__ float s[128];
    float v = z[bb * F + t];
    s[t] = v;
    __syncthreads();
    for (int st = F >> 1; st > 0; st >>= 1) { if (t < st) s[t] += s[t + st]; __syncthreads(); }
    float mu = s[0] / (float)F;
    __syncthreads();
    float d = v - mu;
    s[t] = d * d;
    __syncthreads();
    for (int st = F >> 1; st > 0; st >>= 1) { if (t < st) s[t] += s[t + st]; __syncthreads(); }
    float var = s[0] / (float)F;
    y[bb * F + t] = fmaxf(d * rsqrtf(var + 1e-5f) * g[t] + b[t], 0.f);
}

// ---------------- fc2 + LN + relu + fc3 + sigmoid ----------------
__global__ void head_kernel(const float* __restrict__ y1, const float* __restrict__ w2,
                            const float* __restrict__ b2, const float* __restrict__ g2,
                            const float* __restrict__ bn2, const float* __restrict__ w3,
                            const float* __restrict__ b3, float* __restrict__ out) {
    int b = blockIdx.x, t = threadIdx.x;  // 64 threads
    __shared__ float yr[128];
    yr[t] = y1[b * 128 + t];
    yr[64 + t] = y1[b * 128 + 64 + t];
    __syncthreads();
    float acc = b2[t];
    #pragma unroll 4
    for (int f = 0; f < 128; f++) acc += yr[f] * w2[t * 128 + f];
    __shared__ float s1[64], s2[64];
    s1[t] = acc;
    __syncthreads();
    for (int s = 32; s > 0; s >>= 1) { if (t < s) s1[t] += s1[t + s]; __syncthreads(); }
    float mu = s1[0] / 64.f;
    __syncthreads();
    float d = acc - mu;
    s2[t] = d * d;
    __syncthreads();
    for (int s = 32; s > 0; s >>= 1) { if (t < s) s2[t] += s2[t + s]; __syncthreads(); }
    float var = s2[0] / 64.f;
    float v = fmaxf(d * rsqrtf(var + 1e-5f) * g2[t] + bn2[t], 0.f);
    __syncthreads();
    s1[t] = v * w3[t];
    __syncthreads();
    for (int s = 32; s > 0; s >>= 1) { if (t < s) s1[t] += s1[t + s]; __syncthreads(); }
    if (t == 0) out[b] = 1.f / (1.f + expf(-(s1[0] + b3[0])));
}

// ---------------- launch ----------------
extern "C" void kernel_launch(void* const* d_in, const int* in_sizes, int n_in,
                              void* d_out, int out_size) {
    const float* x1   = (const float*)d_in[0];
    const int*   ei1  = (const int*)d_in[1];
    const float* x2   = (const float*)d_in[3];
    const int*   ei2  = (const int*)d_in[4];
    const float* w1l  = (const float*)d_in[5];
    const float* b1l  = (const float*)d_in[6];
    const float* w1r  = (const float*)d_in[7];
    const float* w2l  = (const float*)d_in[8];
    const float* b2l  = (const float*)d_in[9];
    const float* w2r  = (const float*)d_in[10];
    const float* fc1w = (const float*)d_in[11];
    const float* fc1b = (const float*)d_in[12];
    const float* ln1g = (const float*)d_in[13];
    const float* ln1b = (const float*)d_in[14];
    const float* fc2w = (const float*)d_in[15];
    const float* fc2b = (const float*)d_in[16];
    const float* ln2g = (const float*)d_in[17];
    const float* ln2b = (const float*)d_in[18];
    const float* fc3w = (const float*)d_in[19];
    const float* fc3b = (const float*)d_in[20];
    float* out = (float*)d_out;

    int N1 = in_sizes[0] / FDIM;
    int E1 = in_sizes[1] / 2;
    int N2 = in_sizes[3] / FDIM;
    int E2 = in_sizes[4] / 2;
    int NPG = N1 / BGR;
    int INDIM = KSEL * N2;
    int CH = (NPG + 7) / 8;

    int *rowptr1, *col1, *rowptr2, *col2, *topk, *part1, *part2, *deg1, *deg2;
    float *pq1, *pq2, *pq1b, *pq2b, *o1, *o2, *lastc, *feat, *z1, *y1;
    uint32_t *fAh, *fAl, *fBh, *fBl, *w1h, *w1lo, *w2h, *w2lo;
    u64 *pk;
    cudaGetSymbolAddress((void**)&deg1, g_deg1);
    cudaGetSymbolAddress((void**)&deg2, g_deg2);
    cudaGetSymbolAddress((void**)&rowptr1, g_rowptr1);
    cudaGetSymbolAddress((void**)&col1, g_col1);
    cudaGetSymbolAddress((void**)&rowptr2, g_rowptr2);
    cudaGetSymbolAddress((void**)&col2, g_col2);
    cudaGetSymbolAddress((void**)&part1, g_part1);
    cudaGetSymbolAddress((void**)&part2, g_part2);
    cudaGetSymbolAddress((void**)&fAh, g_fAh);
    cudaGetSymbolAddress((void**)&fAl, g_fAl);
    cudaGetSymbolAddress((void**)&fBh, g_fBh);
    cudaGetSymbolAddress((void**)&fBl, g_fBl);
    cudaGetSymbolAddress((void**)&w1h, g_w1h);
    cudaGetSymbolAddress((void**)&w1lo, g_w1l);
    cudaGetSymbolAddress((void**)&w2h, g_w2h);
    cudaGetSymbolAddress((void**)&w2lo, g_w2l);
    cudaGetSymbolAddress((void**)&pq1, g_pq1);
    cudaGetSymbolAddress((void**)&pq2, g_pq2);
    cudaGetSymbolAddress((void**)&pq1b, g_pq1b);
    cudaGetSymbolAddress((void**)&pq2b, g_pq2b);
    cudaGetSymbolAddress((void**)&o1, g_o1);
    cudaGetSymbolAddress((void**)&o2, g_o2);
    cudaGetSymbolAddress((void**)&lastc, g_lastcol);
    cudaGetSymbolAddress((void**)&pk, g_pk);
    cudaGetSymbolAddress((void**)&topk, g_topk);
    cudaGetSymbolAddress((void**)&feat, g_feat);
    cudaGetSymbolAddress((void**)&z1, g_z1);
    cudaGetSymbolAddress((void**)&y1, g_y1);

    int tiles1 = (N1 + 63) / 64, t16_1 = tiles1 * 4;
    int tiles2 = (N2 + 63) / 64, t16_2 = tiles2 * 4;
    int zmax = (N1 > N2 ? N1 : N2);
    int nb1 = (N1 + 1023) / 1024, nb2 = (N2 + 1023) / 1024;
    int Etot = E1 + E2;

    // --- early independent work (puts interesting kernels in the ncu window) ---
    zero_counts_kernel<<<(zmax + 255) / 256, 256>>>(N1, N2);              // 0
    convW_kernel<<<8, 128>>>(w1l, w1r, 128, w1h, w1lo);                   // 1
    convW_kernel<<<4, 128>>>(w2l, w2r, 64, w2h, w2lo);                    // 2
    convA_kernel<<<(t16_1 + 7) / 8, 256>>>(x1, N1, t16_1, fAh, fAl);      // 3
    gemm_frag_kernel<8, 4><<<tiles1, 256>>>(fAh, fAl, w1h, w1lo, pq1, N1);// 4
    degree2_kernel<<<(Etot + 255) / 256, 256>>>(ei1, E1, ei2, E2);        // 5

    // --- CSR build ---
    block_sum_kernel<<<nb1, 256>>>(deg1, N1, part1);
    block_sum_kernel<<<nb2, 256>>>(deg2, N2, part2);
    scan_part2_kernel<<<2, 128>>>(part1, nb1, rowptr1, N1, part2, nb2, rowptr2, N2);
    write_rowptr_kernel<<<nb1, 1024>>>(deg1, N1, part1, rowptr1);
    write_rowptr_kernel<<<nb2, 1024>>>(deg2, N2, part2, rowptr2);
    scatter2_kernel<<<(Etot + 255) / 256, 256>>>(ei1, E1, ei2, E2);

    // --- graph2 (tiny, private buffers) ---
    convA_kernel<<<(t16_2 + 7) / 8, 256>>>(x2, N2, t16_2, fBh, fBl);
    gemm_frag_kernel<8, 4><<<tiles2, 256>>>(fBh, fBl, w1h, w1lo, pq1b, N2);
    fused_l1_kernel<<<t16_2, 512>>>(pq1b, b1l, rowptr2, col2, fBh, fBl, N2);
    gemm_frag_kernel<4, 4><<<tiles2, 128>>>(fBh, fBl, w2h, w2lo, pq2b, N2);
    fused_l2_kernel<<<((N2 + 1) / 2 * 32 + 255) / 256, 256>>>(pq2b, b2l, rowptr2, col2,
                                                              o2, nullptr, nullptr, N2);

    // --- graph1 ---
    fused_l1_kernel<<<t16_1, 512>>>(pq1, b1l, rowptr1, col1, fAh, fAl, N1);
    gemm_frag_kernel<4, 4><<<tiles1, 128>>>(fAh, fAl, w2h, w2lo, pq2, N1);
    fused_l2_kernel<<<((N1 + 1) / 2 * 32 + 255) / 256, 256>>>(pq2, b2l, rowptr1, col1,
                                                              o1, o2 + (size_t)(N2 - 1) * 64,
                                                              lastc, N1);

    // --- ranking + selected features + MLP head ---
    topk_part_kernel<<<BGR * 8, 512>>>(lastc, pk, NPG, CH);
    topk_merge_kernel<<<BGR, 512>>>(pk, topk, NPG);
    feat_kernel<<<BGR * KSEL, 256>>>(o1, o2, topk, feat, N2);
    fc1_kernel<<<BGR * 128, 256>>>(feat, fc1w, fc1b, z1, INDIM);
    ln_relu_kernel<<<BGR, 128>>>(z1, ln1g, ln1b, y1, 128);
    head_kernel<<<BGR, 64>>>(y1, fc2w, fc2b, ln2g, ln2b, fc3w, fc3b, out);
}

// round 10
// speedup vs baseline: 1.6015x; 1.2000x over previous
#include <cuda_runtime.h>
#include <math.h>
#include <stdint.h>

#define N1CAP 50000
#define E1CAP 1000000
#define N2CAP 256
#define E2CAP 4096
#define FDIM 128
#define BGR 10
#define KSEL 50
#define NN2 199
#define T16MAX 3136

typedef unsigned long long u64;

// ---------------- scratch (device globals; no allocation allowed) ----------------
__device__ int   g_deg1[N1CAP], g_wpos1[N1CAP], g_rowptr1[N1CAP + 1];
__device__ int   g_col1[E1CAP];
__device__ int   g_deg2[N2CAP], g_wpos2[N2CAP], g_rowptr2[N2CAP + 1];
__device__ int   g_col2[E2CAP];
__device__ int   g_part1[128], g_part2[128];
__device__ uint32_t g_fAh[(size_t)T16MAX * 2048];   // graph1 A fragments hi
__device__ uint32_t g_fAl[(size_t)T16MAX * 2048];   // graph1 A fragments lo
__device__ uint32_t g_fBh[16 * 2048], g_fBl[16 * 2048];  // graph2 A fragments
__device__ uint32_t g_w1h[32 * 16 * 64], g_w1l[32 * 16 * 64];  // layer1 W frags (N=256)
__device__ uint32_t g_w2h[16 * 16 * 64], g_w2l[16 * 16 * 64];  // layer2 W frags (N=128)
__device__ float g_pq1[(size_t)N1CAP * 256];
__device__ float g_pq2[(size_t)N1CAP * 128];
__device__ float g_pq1b[256 * 256];
__device__ float g_pq2b[256 * 128];
__device__ float g_o1[(size_t)N1CAP * 64];
__device__ float g_o2[N2CAP * 64];
__device__ float g_lastcol[N1CAP];
__device__ u64   g_pk[BGR * 8 * KSEL];
__device__ int   g_topk[BGR * KSEL];
__device__ float g_feat[BGR * KSEL * NN2];
__device__ float g_z1[BGR * FDIM];
__device__ float g_y1[BGR * FDIM];

// ---------------- tf32 helpers ----------------
__device__ __forceinline__ void tf32split(float v, uint32_t& hi, uint32_t& lo) {
    asm("cvt.rna.tf32.f32 %0, %1;" : "=r"(hi) : "f"(v));
    float l = v - __uint_as_float(hi);
    asm("cvt.rna.tf32.f32 %0, %1;" : "=r"(lo) : "f"(l));
}

#define MMA_TF32(ac, a, b0v, b1v) \
    asm volatile("mma.sync.aligned.m16n8k8.row.col.f32.tf32.tf32.f32 " \
                 "{%0,%1,%2,%3}, {%4,%5,%6,%7}, {%8,%9}, {%0,%1,%2,%3};" \
                 : "+f"((ac)[0]), "+f"((ac)[1]), "+f"((ac)[2]), "+f"((ac)[3]) \
                 : "r"((a)[0]), "r"((a)[1]), "r"((a)[2]), "r"((a)[3]), \
                   "r"(b0v), "r"(b1v))

// ---------------- CSR build ----------------
__global__ void zero_counts_kernel(int n1, int n2) {
    int i = blockIdx.x * blockDim.x + threadIdx.x;
    if (i < n1) { g_deg1[i] = 0; g_wpos1[i] = 0; }
    if (i < n2) { g_deg2[i] = 0; g_wpos2[i] = 0; }
}

__global__ void degree2_kernel(const int* __restrict__ ei1, int E1,
                               const int* __restrict__ ei2, int E2) {
    int e = blockIdx.x * blockDim.x + threadIdx.x;
    if (e < E1) atomicAdd(&g_deg1[ei1[E1 + e]], 1);
    else if (e - E1 < E2) atomicAdd(&g_deg2[ei2[E2 + (e - E1)]], 1);
}

__global__ void block_sum_kernel(const int* __restrict__ deg, int n, int* __restrict__ part) {
    __shared__ int s[256];
    int b = blockIdx.x;
    int base = b * 1024;
    int sum = 0;
    for (int i = threadIdx.x; i < 1024; i += 256) {
        int gi = base + i;
        if (gi < n) sum += deg[gi];
    }
    s[threadIdx.x] = sum;
    __syncthreads();
    for (int st = 128; st > 0; st >>= 1) {
        if (threadIdx.x < st) s[threadIdx.x] += s[threadIdx.x + st];
        __syncthreads();
    }
    if (threadIdx.x == 0) part[b] = s[0];
}

__global__ void scan_part2_kernel(int* __restrict__ p1, int nb1, int* __restrict__ r1, int n1,
                                  int* __restrict__ p2, int nb2, int* __restrict__ r2, int n2) {
    __shared__ int s[128];
    int* part = blockIdx.x ? p2 : p1;
    int* rowptr = blockIdx.x ? r2 : r1;
    int nb = blockIdx.x ? nb2 : nb1;
    int n = blockIdx.x ? n2 : n1;
    int t = threadIdx.x;
    int v = (t < nb) ? part[t] : 0;
    s[t] = v;
    __syncthreads();
    for (int off = 1; off < 128; off <<= 1) {
        int u = (t >= off) ? s[t - off] : 0;
        __syncthreads();
        s[t] += u;
        __syncthreads();
    }
    if (t < nb) part[t] = s[t] - v;
    if (t == 127) rowptr[n] = s[127];
}

__global__ void write_rowptr_kernel(const int* __restrict__ deg, int n,
                                    const int* __restrict__ part, int* __restrict__ rowptr) {
    __shared__ int s[1024];
    int b = blockIdx.x, t = threadIdx.x;
    int gi = b * 1024 + t;
    int v = (gi < n) ? deg[gi] : 0;
    s[t] = v;
    __syncthreads();
    for (int off = 1; off < 1024; off <<= 1) {
        int u = (t >= off) ? s[t - off] : 0;
        __syncthreads();
        s[t] += u;
        __syncthreads();
    }
    if (gi < n) rowptr[gi] = part[b] + s[t] - v;
}

__global__ void scatter2_kernel(const int* __restrict__ ei1, int E1,
                                const int* __restrict__ ei2, int E2) {
    int e = blockIdx.x * blockDim.x + threadIdx.x;
    if (e < E1) {
        int d = ei1[E1 + e];
        int p = atomicAdd(&g_wpos1[d], 1);
        g_col1[g_rowptr1[d] + p] = ei1[e];
    } else if (e - E1 < E2) {
        int ee = e - E1;
        int d = ei2[E2 + ee];
        int p = atomicAdd(&g_wpos2[d], 1);
        g_col2[g_rowptr2[d] + p] = ei2[ee];
    }
}

// ---------------- convert A [n x 128] row-major -> fragment-order hi/lo ----------------
__global__ void convA_kernel(const float* __restrict__ src, int n, int t16tot,
                             uint32_t* __restrict__ dh, uint32_t* __restrict__ dl) {
    int widx = threadIdx.x >> 5, lane = threadIdx.x & 31;
    int T = blockIdx.x * 8 + widx;
    if (T >= t16tot) return;
    int gid = lane >> 2, tig = lane & 3;
    long long r0 = (long long)T * 16 + gid, r1 = r0 + 8;
    bool ok0 = r0 < n, ok1 = r1 < n;
    for (int k8 = 0; k8 < 16; k8++) {
        int c0 = k8 * 8 + tig, c1 = c0 + 4;
        float v00 = ok0 ? src[r0 * 128 + c0] : 0.f;
        float v01 = ok0 ? src[r0 * 128 + c1] : 0.f;
        float v10 = ok1 ? src[r1 * 128 + c0] : 0.f;
        float v11 = ok1 ? src[r1 * 128 + c1] : 0.f;
        uint4 h, l;
        tf32split(v00, h.x, l.x);
        tf32split(v10, h.y, l.y);
        tf32split(v01, h.z, l.z);
        tf32split(v11, h.w, l.w);
        size_t idx = ((size_t)T * 16 + k8) * 128 + lane * 4;
        *(uint4*)(dh + idx) = h;
        *(uint4*)(dl + idx) = l;
    }
}

// ---------------- convert stacked weights [Wa;Wb] -> fragment-order hi/lo ----------------
__global__ void convW_kernel(const float* __restrict__ Wa, const float* __restrict__ Wb,
                             int Nhalf, uint32_t* __restrict__ dh, uint32_t* __restrict__ dl) {
    int widx = threadIdx.x >> 5, lane = threadIdx.x & 31;
    int nt = blockIdx.x * 4 + widx;
    int ntTot = (2 * Nhalf) / 8;
    if (nt >= ntTot) return;
    int gid = lane >> 2, tig = lane & 3;
    int o = nt * 8 + gid;
    const float* Wrow = (o < Nhalf) ? (Wa + (size_t)o * 128) : (Wb + (size_t)(o - Nhalf) * 128);
    for (int k8 = 0; k8 < 16; k8++) {
        float v0 = Wrow[k8 * 8 + tig];
        float v1 = Wrow[k8 * 8 + tig + 4];
        uint2 h, l;
        tf32split(v0, h.x, l.x);
        tf32split(v1, h.y, l.y);
        size_t idx = ((size_t)nt * 16 + k8) * 64 + lane * 2;
        *(uint2*)(dh + idx) = h;
        *(uint2*)(dl + idx) = l;
    }
}

// ---------------- GEMM: out[m, o] = sum_k A[m,k] W[o,k], 3xTF32, no smem ----------------
template <int WARPS, int NTW>
__global__ void __launch_bounds__(WARPS * 32)
gemm_frag_kernel(const uint32_t* __restrict__ Ah, const uint32_t* __restrict__ Al,
                 const uint32_t* __restrict__ Bh, const uint32_t* __restrict__ Bl,
                 float* __restrict__ out, int n) {
    constexpr int N = WARPS * NTW * 8;
    int tid = threadIdx.x, wid = tid >> 5, lane = tid & 31;
    int gid = lane >> 2, tig = lane & 3;
    long long mbase = (long long)blockIdx.x * 64;
    int T0 = blockIdx.x * 4;

    float acc[4][NTW][4];
    #pragma unroll
    for (int mt = 0; mt < 4; mt++)
        #pragma unroll
        for (int nt = 0; nt < NTW; nt++)
            #pragma unroll
            for (int j = 0; j < 4; j++) acc[mt][nt][j] = 0.f;

    for (int k8 = 0; k8 < 16; k8++) {
        uint32_t ah[4][4], al[4][4];
        #pragma unroll
        for (int mt = 0; mt < 4; mt++) {
            size_t ai = ((size_t)(T0 + mt) * 16 + k8) * 128 + lane * 4;
            uint4 h = *(const uint4*)(Ah + ai);
            uint4 l = *(const uint4*)(Al + ai);
            ah[mt][0] = h.x; ah[mt][1] = h.y; ah[mt][2] = h.z; ah[mt][3] = h.w;
            al[mt][0] = l.x; al[mt][1] = l.y; al[mt][2] = l.z; al[mt][3] = l.w;
        }
        #pragma unroll
        for (int nt = 0; nt < NTW; nt++) {
            int gnt = wid * NTW + nt;
            size_t bi = ((size_t)gnt * 16 + k8) * 64 + lane * 2;
            uint2 bh = *(const uint2*)(Bh + bi);
            uint2 bl2 = *(const uint2*)(Bl + bi);
            #pragma unroll
            for (int mt = 0; mt < 4; mt++) {
                MMA_TF32(acc[mt][nt], ah[mt], bh.x, bh.y);
                MMA_TF32(acc[mt][nt], ah[mt], bl2.x, bl2.y);
                MMA_TF32(acc[mt][nt], al[mt], bh.x, bh.y);
            }
        }
    }

    #pragma unroll
    for (int nt = 0; nt < NTW; nt++) {
        int col = wid * NTW * 8 + nt * 8 + tig * 2;
        #pragma unroll
        for (int mt = 0; mt < 4; mt++) {
            long long r0 = mbase + mt * 16 + gid;
            long long r1 = r0 + 8;
            if (r0 < n) {
                float2 v = {acc[mt][nt][0], acc[mt][nt][1]};
                *(float2*)(out + r0 * N + col) = v;
            }
            if (r1 < n) {
                float2 v = {acc[mt][nt][2], acc[mt][nt][3]};
                *(float2*)(out + r1 * N + col) = v;
            }
        }
    }
}

// ---------------- fused layer1: agg(mean of pq[.,0:128]) + self + bias + relu -> fragments ----
__global__ void __launch_bounds__(512)
fused_l1_kernel(const float* __restrict__ pq, const float* __restrict__ bias,
                const int* __restrict__ rowptr, const int* __restrict__ col,
                uint32_t* __restrict__ dh, uint32_t* __restrict__ dl, int n) {
    __shared__ float ht[16][132];
    int w = threadIdx.x >> 5, lane = threadIdx.x & 31;
    int T = blockIdx.x;
    int node = T * 16 + w;
    float4 r = make_float4(0.f, 0.f, 0.f, 0.f);
    if (node < n) {
        int s = rowptr[node], e = rowptr[node + 1];
        const float4* s4 = (const float4*)pq;
        float4 acc = make_float4(0.f, 0.f, 0.f, 0.f);
        #pragma unroll 4
        for (int j = s; j < e; j++) {
            float4 v = s4[(long long)col[j] * 64 + lane];
            acc.x += v.x; acc.y += v.y; acc.z += v.z; acc.w += v.w;
        }
        float inv = 1.0f / (float)max(e - s, 1);
        float4 q = s4[(long long)node * 64 + 32 + lane];
        float4 b = ((const float4*)bias)[lane];
        r.x = fmaxf(acc.x * inv + q.x + b.x, 0.f);
        r.y = fmaxf(acc.y * inv + q.y + b.y, 0.f);
        r.z = fmaxf(acc.z * inv + q.z + b.z, 0.f);
        r.w = fmaxf(acc.w * inv + q.w + b.w, 0.f);
    }
    ht[w][lane * 4] = r.x;
    ht[w][lane * 4 + 1] = r.y;
    ht[w][lane * 4 + 2] = r.z;
    ht[w][lane * 4 + 3] = r.w;
    __syncthreads();
    int k8 = w;
    int gid = lane >> 2, tig = lane & 3;
    int c0 = k8 * 8 + tig, c1 = c0 + 4;
    float v00 = ht[gid][c0], v10 = ht[gid + 8][c0];
    float v01 = ht[gid][c1], v11 = ht[gid + 8][c1];
    uint4 h, l;
    tf32split(v00, h.x, l.x);
    tf32split(v10, h.y, l.y);
    tf32split(v01, h.z, l.z);
    tf32split(v11, h.w, l.w);
    size_t idx = ((size_t)T * 16 + k8) * 128 + lane * 4;
    *(uint4*)(dh + idx) = h;
    *(uint4*)(dl + idx) = l;
}

// ---------------- fused layer2: agg + self + bias + relu -> o (+lastcol) ----------------
__global__ void fused_l2_kernel(const float* __restrict__ pq2, const float* __restrict__ bias,
                                const int* __restrict__ rowptr, const int* __restrict__ col,
                                float* __restrict__ o, const float* __restrict__ o2last,
                                float* __restrict__ lastc, int n) {
    __shared__ float bl[64];
    if (o2last != nullptr && threadIdx.x < 64) bl[threadIdx.x] = o2last[threadIdx.x];
    __syncthreads();
    int gt = blockIdx.x * blockDim.x + threadIdx.x;
    int wrp = gt >> 5, lane = gt & 31;
    int node = wrp * 2 + (lane >> 4);
    int li = lane & 15;
    if (node >= n) return;
    int s = rowptr[node], e = rowptr[node + 1];
    const float4* s4 = (const float4*)pq2;
    float4 acc = make_float4(0.f, 0.f, 0.f, 0.f);
    #pragma unroll 4
    for (int j = s; j < e; j++) {
        float4 v = s4[(long long)col[j] * 32 + li];
        acc.x += v.x; acc.y += v.y; acc.z += v.z; acc.w += v.w;
    }
    float inv = 1.0f / (float)max(e - s, 1);
    float4 q = s4[(long long)node * 32 + 16 + li];
    float4 b = ((const float4*)bias)[li];
    float4 r;
    r.x = fmaxf(acc.x * inv + q.x + b.x, 0.f);
    r.y = fmaxf(acc.y * inv + q.y + b.y, 0.f);
    r.z = fmaxf(acc.z * inv + q.z + b.z, 0.f);
    r.w = fmaxf(acc.w * inv + q.w + b.w, 0.f);
    ((float4*)o)[(long long)node * 16 + li] = r;
    if (lastc != nullptr) {
        float4 blv = ((const float4*)bl)[li];
        float t0 = r.x - blv.x, t1 = r.y - blv.y, t2 = r.z - blv.z, t3 = r.w - blv.w;
        float d = t0 * t0 + t1 * t1 + t2 * t2 + t3 * t3;
        #pragma unroll
        for (int off = 8; off; off >>= 1) d += __shfl_xor_sync(0xffffffffu, d, off);
        if (li == 0) lastc[node] = sqrtf(fmaxf(d, 0.f));
    }
}

// ---------------- top-K: per-chunk bitonic (exact), then merge ----------------
__global__ void topk_part_kernel(const float* __restrict__ lastc, u64* __restrict__ pk,
                                 int npg, int ch) {
    __shared__ u64 key[1024];
    int g = blockIdx.x >> 3, c = blockIdx.x & 7;
    int base = c * ch;
    for (int i = threadIdx.x; i < 1024; i += blockDim.x) {
        int li = base + i;
        u64 k = 0xFFFFFFFFFFFFFFFFull;
        if (i < ch && li < npg) {
            unsigned u = __float_as_uint(lastc[g * npg + li]);
            u = (u & 0x80000000u) ? ~u : (u | 0x80000000u);
            u = ~u;
            k = ((u64)u << 32) | (unsigned)li;
        }
        key[i] = k;
    }
    __syncthreads();
    for (int size = 2; size <= 1024; size <<= 1) {
        for (int stride = size >> 1; stride > 0; stride >>= 1) {
            for (int i = threadIdx.x; i < 1024; i += blockDim.x) {
                int j = i ^ stride;
                if (j > i) {
                    u64 a = key[i], b = key[j];
                    bool up = ((i & size) == 0);
                    if ((a > b) == up) { key[i] = b; key[j] = a; }
                }
            }
            __syncthreads();
        }
    }
    if (threadIdx.x < KSEL) pk[(g * 8 + c) * KSEL + threadIdx.x] = key[threadIdx.x];
}

__global__ void topk_merge_kernel(const u64* __restrict__ pk, int* __restrict__ topk, int npg) {
    __shared__ u64 key[512];
    int g = blockIdx.x;
    for (int i = threadIdx.x; i < 512; i += blockDim.x)
        key[i] = (i < 8 * KSEL) ? pk[g * 8 * KSEL + i] : 0xFFFFFFFFFFFFFFFFull;
    __syncthreads();
    for (int size = 2; size <= 512; size <<= 1) {
        for (int stride = size >> 1; stride > 0; stride >>= 1) {
            for (int i = threadIdx.x; i < 512; i += blockDim.x) {
                int j = i ^ stride;
                if (j > i) {
                    u64 a = key[i], b = key[j];
                    bool up = ((i & size) == 0);
                    if ((a > b) == up) { key[i] = b; key[j] = a; }
                }
            }
            __syncthreads();
        }
    }
    if (threadIdx.x < KSEL)
        topk[g * KSEL + threadIdx.x] = g * npg + (int)(key[threadIdx.x] & 0xFFFFFFFFull);
}

// ---------------- full dist rows only for the B*K selected nodes ----------------
__global__ void feat_kernel(const float* __restrict__ o1, const float* __restrict__ o2,
                            const int* __restrict__ topk, float* __restrict__ feat, int n2) {
    __shared__ float a[64];
    int s = blockIdx.x;
    int node = topk[s];
    if (threadIdx.x < 64) a[threadIdx.x] = o1[(long long)node * 64 + threadIdx.x];
    __syncthreads();
    for (int j = threadIdx.x; j < n2; j += blockDim.x) {
        float d = 0.f;
        #pragma unroll
        for (int f = 0; f < 64; f++) {
            float t = a[f] - o2[j * 64 + f];
            d += t * t;
        }
        feat[s * n2 + j] = sqrtf(fmaxf(d, 0.f));
    }
}

// ---------------- fc1 ----------------
__global__ void fc1_kernel(const float* __restrict__ feat, const float* __restrict__ w,
                           const float* __restrict__ bias, float* __restrict__ z, int indim) {
    int b = blockIdx.x >> 7, o = blockIdx.x & 127;
    const float* fr = feat + (long long)b * indim;
    const float* wr = w + (long long)o * indim;
    float acc = 0.f;
    for (int i = threadIdx.x; i < indim; i += blockDim.x) acc += fr[i] * wr[i];
    __shared__ float red[256];
    red[threadIdx.x] = acc;
    __syncthreads();
    for (int s = 128; s > 0; s >>= 1) {
        if (threadIdx.x < s) red[threadIdx.x] += red[threadIdx.x + s];
        __syncthreads();
    }
    if (threadIdx.x == 0) z[b * 128 + o] = red[0] + bias[o];
}

// ---------------- layernorm + relu ----------------
__global__ void ln_relu_kernel(const float* __restrict__ z, const float* __restrict__ g,
                               const float* __restrict__ b, float* __restrict__ y, int F) {
    int bb = blockIdx.x, t = threadIdx.x;
    __shared__ float s[128];
    float v = z[bb * F + t];
    s[t] = v;
    __syncthreads();
    for (int st = F >> 1; st > 0; st >>= 1) { if (t < st) s[t] += s[t + st]; __syncthreads(); }
    float mu = s[0] / (float)F;
    __syncthreads();
    float d = v - mu;
    s[t] = d * d;
    __syncthreads();
    for (int st = F >> 1; st > 0; st >>= 1) { if (t < st) s[t] += s[t + st]; __syncthreads(); }
    float var = s[0] / (float)F;
    y[bb * F + t] = fmaxf(d * rsqrtf(var + 1e-5f) * g[t] + b[t], 0.f);
}

// ---------------- fc2 + LN + relu + fc3 + sigmoid ----------------
__global__ void head_kernel(const float* __restrict__ y1, const float* __restrict__ w2,
                            const float* __restrict__ b2, const float* __restrict__ g2,
                            const float* __restrict__ bn2, const float* __restrict__ w3,
                            const float* __restrict__ b3, float* __restrict__ out) {
    int b = blockIdx.x, t = threadIdx.x;  // 64 threads
    __shared__ float yr[128];
    yr[t] = y1[b * 128 + t];
    yr[64 + t] = y1[b * 128 + 64 + t];
    __syncthreads();
    float acc = b2[t];
    #pragma unroll 4
    for (int f = 0; f < 128; f++) acc += yr[f] * w2[t * 128 + f];
    __shared__ float s1[64], s2[64];
    s1[t] = acc;
    __syncthreads();
    for (int s = 32; s > 0; s >>= 1) { if (t < s) s1[t] += s1[t + s]; __syncthreads(); }
    float mu = s1[0] / 64.f;
    __syncthreads();
    float d = acc - mu;
    s2[t] = d * d;
    __syncthreads();
    for (int s = 32; s > 0; s >>= 1) { if (t < s) s2[t] += s2[t + s]; __syncthreads(); }
    float var = s2[0] / 64.f;
    float v = fmaxf(d * rsqrtf(var + 1e-5f) * g2[t] + bn2[t], 0.f);
    __syncthreads();
    s1[t] = v * w3[t];
    __syncthreads();
    for (int s = 32; s > 0; s >>= 1) { if (t < s) s1[t] += s1[t + s]; __syncthreads(); }
    if (t == 0) out[b] = 1.f / (1.f + expf(-(s1[0] + b3[0])));
}

// ---------------- launch ----------------
extern "C" void kernel_launch(void* const* d_in, const int* in_sizes, int n_in,
                              void* d_out, int out_size) {
    const float* x1   = (const float*)d_in[0];
    const int*   ei1  = (const int*)d_in[1];
    const float* x2   = (const float*)d_in[3];
    const int*   ei2  = (const int*)d_in[4];
    const float* w1l  = (const float*)d_in[5];
    const float* b1l  = (const float*)d_in[6];
    const float* w1r  = (const float*)d_in[7];
    const float* w2l  = (const float*)d_in[8];
    const float* b2l  = (const float*)d_in[9];
    const float* w2r  = (const float*)d_in[10];
    const float* fc1w = (const float*)d_in[11];
    const float* fc1b = (const float*)d_in[12];
    const float* ln1g = (const float*)d_in[13];
    const float* ln1b = (const float*)d_in[14];
    const float* fc2w = (const float*)d_in[15];
    const float* fc2b = (const float*)d_in[16];
    const float* ln2g = (const float*)d_in[17];
    const float* ln2b = (const float*)d_in[18];
    const float* fc3w = (const float*)d_in[19];
    const float* fc3b = (const float*)d_in[20];
    float* out = (float*)d_out;

    int N1 = in_sizes[0] / FDIM;
    int E1 = in_sizes[1] / 2;
    int N2 = in_sizes[3] / FDIM;
    int E2 = in_sizes[4] / 2;
    int NPG = N1 / BGR;
    int INDIM = KSEL * N2;
    int CH = (NPG + 7) / 8;

    int *rowptr1, *col1, *rowptr2, *col2, *topk, *part1, *part2, *deg1, *deg2;
    float *pq1, *pq2, *pq1b, *pq2b, *o1, *o2, *lastc, *feat, *z1, *y1;
    uint32_t *fAh, *fAl, *fBh, *fBl, *w1h, *w1lo, *w2h, *w2lo;
    u64 *pk;
    cudaGetSymbolAddress((void**)&deg1, g_deg1);
    cudaGetSymbolAddress((void**)&deg2, g_deg2);
    cudaGetSymbolAddress((void**)&rowptr1, g_rowptr1);
    cudaGetSymbolAddress((void**)&col1, g_col1);
    cudaGetSymbolAddress((void**)&rowptr2, g_rowptr2);
    cudaGetSymbolAddress((void**)&col2, g_col2);
    cudaGetSymbolAddress((void**)&part1, g_part1);
    cudaGetSymbolAddress((void**)&part2, g_part2);
    cudaGetSymbolAddress((void**)&fAh, g_fAh);
    cudaGetSymbolAddress((void**)&fAl, g_fAl);
    cudaGetSymbolAddress((void**)&fBh, g_fBh);
    cudaGetSymbolAddress((void**)&fBl, g_fBl);
    cudaGetSymbolAddress((void**)&w1h, g_w1h);
    cudaGetSymbolAddress((void**)&w1lo, g_w1l);
    cudaGetSymbolAddress((void**)&w2h, g_w2h);
    cudaGetSymbolAddress((void**)&w2lo, g_w2l);
    cudaGetSymbolAddress((void**)&pq1, g_pq1);
    cudaGetSymbolAddress((void**)&pq2, g_pq2);
    cudaGetSymbolAddress((void**)&pq1b, g_pq1b);
    cudaGetSymbolAddress((void**)&pq2b, g_pq2b);
    cudaGetSymbolAddress((void**)&o1, g_o1);
    cudaGetSymbolAddress((void**)&o2, g_o2);
    cudaGetSymbolAddress((void**)&lastc, g_lastcol);
    cudaGetSymbolAddress((void**)&pk, g_pk);
    cudaGetSymbolAddress((void**)&topk, g_topk);
    cudaGetSymbolAddress((void**)&feat, g_feat);
    cudaGetSymbolAddress((void**)&z1, g_z1);
    cudaGetSymbolAddress((void**)&y1, g_y1);

    // lazily-created side streams + fork/join events (no device memory involved;
    // identical GPU work every call — creation happens on the first, uncaptured run)
    static cudaStream_t sCSR = nullptr, sG2 = nullptr;
    static cudaEvent_t evFork, evW, evCSR, evG2;
    if (sCSR == nullptr) {
        cudaStreamCreateWithFlags(&sCSR, cudaStreamNonBlocking);
        cudaStreamCreateWithFlags(&sG2, cudaStreamNonBlocking);
        cudaEventCreateWithFlags(&evFork, cudaEventDisableTiming);
        cudaEventCreateWithFlags(&evW, cudaEventDisableTiming);
        cudaEventCreateWithFlags(&evCSR, cudaEventDisableTiming);
        cudaEventCreateWithFlags(&evG2, cudaEventDisableTiming);
    }

    int tiles1 = (N1 + 63) / 64, t16_1 = tiles1 * 4;
    int tiles2 = (N2 + 63) / 64, t16_2 = tiles2 * 4;
    int zmax = (N1 > N2 ? N1 : N2);
    int nb1 = (N1 + 1023) / 1024, nb2 = (N2 + 1023) / 1024;
    int Etot = E1 + E2;

    // ---- fork ----
    cudaEventRecord(evFork, 0);

    // ---- branch CSR (sCSR): full CSR build, independent of features ----
    cudaStreamWaitEvent(sCSR, evFork, 0);
    zero_counts_kernel<<<(zmax + 255) / 256, 256, 0, sCSR>>>(N1, N2);
    degree2_kernel<<<(Etot + 255) / 256, 256, 0, sCSR>>>(ei1, E1, ei2, E2);
    block_sum_kernel<<<nb1, 256, 0, sCSR>>>(deg1, N1, part1);
    block_sum_kernel<<<nb2, 256, 0, sCSR>>>(deg2, N2, part2);
    scan_part2_kernel<<<2, 128, 0, sCSR>>>(part1, nb1, rowptr1, N1, part2, nb2, rowptr2, N2);
    write_rowptr_kernel<<<nb1, 1024, 0, sCSR>>>(deg1, N1, part1, rowptr1);
    write_rowptr_kernel<<<nb2, 1024, 0, sCSR>>>(deg2, N2, part2, rowptr2);
    scatter2_kernel<<<(Etot + 255) / 256, 256, 0, sCSR>>>(ei1, E1, ei2, E2);
    cudaEventRecord(evCSR, sCSR);

    // ---- main branch (s0): weights + graph1 layer-1 transform ----
    convW_kernel<<<8, 128>>>(w1l, w1r, 128, w1h, w1lo);
    convW_kernel<<<4, 128>>>(w2l, w2r, 64, w2h, w2lo);
    cudaEventRecord(evW, 0);
    convA_kernel<<<(t16_1 + 7) / 8, 256>>>(x1, N1, t16_1, fAh, fAl);
    gemm_frag_kernel<8, 4><<<tiles1, 256>>>(fAh, fAl, w1h, w1lo, pq1, N1);

    // ---- branch graph2 (sG2): full graph2 GNN on private buffers ----
    cudaStreamWaitEvent(sG2, evFork, 0);
    convA_kernel<<<(t16_2 + 7) / 8, 256, 0, sG2>>>(x2, N2, t16_2, fBh, fBl);
    cudaStreamWaitEvent(sG2, evW, 0);
    gemm_frag_kernel<8, 4><<<tiles2, 256, 0, sG2>>>(fBh, fBl, w1h, w1lo, pq1b, N2);
    cudaStreamWaitEvent(sG2, evCSR, 0);
    fused_l1_kernel<<<t16_2, 512, 0, sG2>>>(pq1b, b1l, rowptr2, col2, fBh, fBl, N2);
    gemm_frag_kernel<4, 4><<<tiles2, 128, 0, sG2>>>(fBh, fBl, w2h, w2lo, pq2b, N2);
    fused_l2_kernel<<<((N2 + 1) / 2 * 32 + 255) / 256, 256, 0, sG2>>>(
        pq2b, b2l, rowptr2, col2, o2, nullptr, nullptr, N2);
    cudaEventRecord(evG2, sG2);

    // ---- main branch continues: graph1 layers (joins CSR, then graph2) ----
    cudaStreamWaitEvent(0, evCSR, 0);
    fused_l1_kernel<<<t16_1, 512>>>(pq1, b1l, rowptr1, col1, fAh, fAl, N1);
    gemm_frag_kernel<4, 4><<<tiles1, 128>>>(fAh, fAl, w2h, w2lo, pq2, N1);
    cudaStreamWaitEvent(0, evG2, 0);
    fused_l2_kernel<<<((N1 + 1) / 2 * 32 + 255) / 256, 256>>>(
        pq2, b2l, rowptr1, col1, o1, o2 + (size_t)(N2 - 1) * 64, lastc, N1);

    // ---- ranking + selected features + MLP head ----
    topk_part_kernel<<<BGR * 8, 512>>>(lastc, pk, NPG, CH);
    topk_merge_kernel<<<BGR, 512>>>(pk, topk, NPG);
    feat_kernel<<<BGR * KSEL, 256>>>(o1, o2, topk, feat, N2);
    fc1_kernel<<<BGR * 128, 256>>>(feat, fc1w, fc1b, z1, INDIM);
    ln_relu_kernel<<<BGR, 128>>>(z1, ln1g, ln1b, y1, 128);
    head_kernel<<<BGR, 64>>>(y1, fc2w, fc2b, ln2g, ln2b, fc3w, fc3b, out);
}